// round 1
// baseline (speedup 1.0000x reference)
#include <cuda_runtime.h>
#include <math.h>

#define NB 2
#define TT 32
#define LL 256
#define DD 768
#define HH 12
#define HD 64
#define FFW_ 3072
#define NLAYER 4
#define NTOK (NB*TT*LL)   // 16384

// ---------------- scratch (device globals, no allocation) ----------------
__device__ float g_x[(size_t)NTOK*DD];     // LN output
__device__ float g_q[(size_t)NTOK*DD];
__device__ float g_k[(size_t)NTOK*DD];
__device__ float g_v[(size_t)NTOK*DD];
__device__ float g_att[(size_t)NTOK*DD];
__device__ float g_ff[(size_t)NTOK*FFW_];

// ---------------- LayerNorm ----------------
__global__ void ln_kernel(const float* __restrict__ h, const float* __restrict__ sc,
                          const float* __restrict__ bi, float* __restrict__ x)
{
    int row = blockIdx.x;
    const float* hr = h + (size_t)row * DD;
    float* xr = x + (size_t)row * DD;
    int tid = threadIdx.x; // 256 threads, 3 elems each (768)
    float v0 = hr[tid], v1 = hr[tid + 256], v2 = hr[tid + 512];
    __shared__ float red[256];
    red[tid] = v0 + v1 + v2;
    __syncthreads();
    for (int o = 128; o > 0; o >>= 1) {
        if (tid < o) red[tid] += red[tid + o];
        __syncthreads();
    }
    float mean = red[0] * (1.0f / DD);
    __syncthreads();
    float d0 = v0 - mean, d1 = v1 - mean, d2 = v2 - mean;
    red[tid] = d0 * d0 + d1 * d1 + d2 * d2;
    __syncthreads();
    for (int o = 128; o > 0; o >>= 1) {
        if (tid < o) red[tid] += red[tid + o];
        __syncthreads();
    }
    float rstd = rsqrtf(red[0] * (1.0f / DD) + 1e-5f);
    xr[tid]       = d0 * rstd * sc[tid]       + bi[tid];
    xr[tid + 256] = d1 * rstd * sc[tid + 256] + bi[tid + 256];
    xr[tid + 512] = d2 * rstd * sc[tid + 512] + bi[tid + 512];
}

// ---------------- GEMM: C[M,Nc] = A[M,Kd] @ W[Kd,Nc] (+epilogue) ----------------
// EPI 0: plain store
// EPI 1: C = gelu_tanh(acc + bias)
// EPI 2: C = C + acc + bias   (residual accumulate)
__device__ __forceinline__ float gelu_tanh(float x)
{
    float x3 = x * x * x;
    return 0.5f * x * (1.0f + tanhf(0.7978845608028654f * (x + 0.044715f * x3)));
}

template <int EPI>
__global__ void __launch_bounds__(256) gemm_kernel(
    const float* __restrict__ A, const float* __restrict__ W,
    const float* __restrict__ bias, float* __restrict__ C,
    int Kd, int Nc)
{
    __shared__ float As[16][132];   // padded, stored transposed
    __shared__ float Bs[16][128];
    const int bm = blockIdx.y * 128;
    const int bn = blockIdx.x * 128;
    const int tid = threadIdx.x;
    const int tx = tid & 15, ty = tid >> 4;
    const int arow = tid >> 2;
    const int acol = (tid & 3) << 2;
    const int brow = tid >> 5;
    const int bcol = (tid & 31) << 2;

    float acc[8][8];
#pragma unroll
    for (int i = 0; i < 8; i++)
#pragma unroll
        for (int j = 0; j < 8; j++) acc[i][j] = 0.f;

    const float* Aptr = A + (size_t)bm * Kd;

    for (int k0 = 0; k0 < Kd; k0 += 16) {
#pragma unroll
        for (int r = 0; r < 2; r++) {
            int row = arow + r * 64;
            float4 va = *(const float4*)(Aptr + (size_t)row * Kd + k0 + acol);
            As[acol + 0][row] = va.x;
            As[acol + 1][row] = va.y;
            As[acol + 2][row] = va.z;
            As[acol + 3][row] = va.w;
        }
#pragma unroll
        for (int r = 0; r < 2; r++) {
            int row = brow + r * 8;
            *(float4*)&Bs[row][bcol] = *(const float4*)(W + (size_t)(k0 + row) * Nc + bn + bcol);
        }
        __syncthreads();
#pragma unroll
        for (int k = 0; k < 16; k++) {
            float a[8], b[8];
            *(float4*)&a[0] = *(const float4*)&As[k][ty * 8];
            *(float4*)&a[4] = *(const float4*)&As[k][ty * 8 + 4];
            *(float4*)&b[0] = *(const float4*)&Bs[k][tx * 8];
            *(float4*)&b[4] = *(const float4*)&Bs[k][tx * 8 + 4];
#pragma unroll
            for (int i = 0; i < 8; i++)
#pragma unroll
                for (int j = 0; j < 8; j++) acc[i][j] += a[i] * b[j];
        }
        __syncthreads();
    }

#pragma unroll
    for (int i = 0; i < 8; i++) {
        size_t base = (size_t)(bm + ty * 8 + i) * Nc + bn + tx * 8;
#pragma unroll
        for (int j = 0; j < 8; j += 4) {
            float4 o;
            o.x = acc[i][j]; o.y = acc[i][j + 1]; o.z = acc[i][j + 2]; o.w = acc[i][j + 3];
            if (EPI == 1) {
                float4 bb = *(const float4*)&bias[bn + tx * 8 + j];
                o.x = gelu_tanh(o.x + bb.x);
                o.y = gelu_tanh(o.y + bb.y);
                o.z = gelu_tanh(o.z + bb.z);
                o.w = gelu_tanh(o.w + bb.w);
            } else if (EPI == 2) {
                float4 bb = *(const float4*)&bias[bn + tx * 8 + j];
                float4 cc = *(const float4*)&C[base + j];
                o.x += bb.x + cc.x;
                o.y += bb.y + cc.y;
                o.z += bb.z + cc.z;
                o.w += bb.w + cc.w;
            }
            *(float4*)&C[base + j] = o;
        }
    }
}

// ---------------- Time attention: softmax over T=32 per (b,l,h) ----------------
// grid (B*L, H), block 32 (one warp). Lane = query t.
__global__ void __launch_bounds__(32) attn_time_kernel(
    const float* __restrict__ q, const float* __restrict__ k,
    const float* __restrict__ v, float* __restrict__ o)
{
    __shared__ float Ks[32][64];
    __shared__ float Vs[32][64];
    __shared__ float Qs[64][33];   // transposed + padded (also reused for output)
    int bl = blockIdx.x;           // 0..B*L-1
    int h = blockIdx.y;            // 0..H-1
    int b = bl / LL, l = bl % LL;
    int tid = threadIdx.x;         // 0..31
    size_t colbase = (size_t)h * HD;

    for (int e = tid; e < 32 * 64; e += 32) {
        int j = e >> 6, d = e & 63;
        size_t off = ((size_t)(b * TT + j) * LL + l) * DD + colbase + d;
        Ks[j][d] = k[off];
        Vs[j][d] = v[off];
        Qs[d][j] = q[off];
    }
    __syncwarp();

    float qr[64];
#pragma unroll
    for (int d = 0; d < 64; d++) qr[d] = Qs[d][tid];

    float sc_[32];
#pragma unroll 4
    for (int j = 0; j < 32; j++) {
        float s = 0.f;
        const float4* kr = (const float4*)Ks[j];
#pragma unroll
        for (int d4 = 0; d4 < 16; d4++) {
            float4 kk = kr[d4];
            s += qr[d4 * 4 + 0] * kk.x + qr[d4 * 4 + 1] * kk.y
               + qr[d4 * 4 + 2] * kk.z + qr[d4 * 4 + 3] * kk.w;
        }
        sc_[j] = s * 0.125f;
    }
    float m = sc_[0];
#pragma unroll
    for (int j = 1; j < 32; j++) m = fmaxf(m, sc_[j]);
    float lsum = 0.f;
#pragma unroll
    for (int j = 0; j < 32; j++) { sc_[j] = __expf(sc_[j] - m); lsum += sc_[j]; }
    float inv = 1.0f / lsum;

#pragma unroll
    for (int d4 = 0; d4 < 16; d4++) {
        float ax = 0.f, ay = 0.f, az = 0.f, aw = 0.f;
#pragma unroll
        for (int j = 0; j < 32; j++) {
            float4 vv = ((const float4*)Vs[j])[d4];
            float w = sc_[j];
            ax += w * vv.x; ay += w * vv.y; az += w * vv.z; aw += w * vv.w;
        }
        Qs[d4 * 4 + 0][tid] = ax * inv;
        Qs[d4 * 4 + 1][tid] = ay * inv;
        Qs[d4 * 4 + 2][tid] = az * inv;
        Qs[d4 * 4 + 3][tid] = aw * inv;
    }
    __syncwarp();
    for (int e = tid; e < 32 * 64; e += 32) {
        int j = e >> 6, d = e & 63;
        o[((size_t)(b * TT + j) * LL + l) * DD + colbase + d] = Qs[d][j];
    }
}

// ---------------- Space attention: softmax over L=256 per (b,t,h) ----------------
// grid B*T*H, block 256. Thread = query l. Online softmax, K/V in 64-row chunks.
#define SPACE_SMEM ((64 * 257 + 64 * 64 + 64 * 64) * 4)
__global__ void __launch_bounds__(256) attn_space_kernel(
    const float* __restrict__ q, const float* __restrict__ k,
    const float* __restrict__ v, float* __restrict__ o)
{
    extern __shared__ float sm[];
    float(*Qs)[257] = (float(*)[257])sm;     // [64][257] transposed + padded
    float* Ks = sm + 64 * 257;               // [64][64]
    float* Vs = Ks + 64 * 64;                // [64][64]
    int gid = blockIdx.x;                    // (b*T + t)*H + h
    int h = gid % HH;
    int bt = gid / HH;
    int tid = threadIdx.x;                   // query l
    size_t rowbase = (size_t)bt * LL;
    size_t colbase = (size_t)h * HD;

    for (int e = tid; e < 256 * 64; e += 256) {
        int j = e >> 6, d = e & 63;
        Qs[d][j] = q[(rowbase + j) * DD + colbase + d];
    }
    __syncthreads();

    float qr[64];
#pragma unroll
    for (int d = 0; d < 64; d++) qr[d] = Qs[d][tid];

    float m = -1e30f, lsum = 0.f;
    float acc[64];
#pragma unroll
    for (int d = 0; d < 64; d++) acc[d] = 0.f;

    for (int c0 = 0; c0 < LL; c0 += 64) {
        __syncthreads();
        for (int e = tid; e < 64 * 64; e += 256) {
            int j = e >> 6, d = e & 63;
            size_t off = (rowbase + c0 + j) * DD + colbase + d;
            Ks[e] = k[off];
            Vs[e] = v[off];
        }
        __syncthreads();
        for (int j = 0; j < 64; j++) {
            float s = 0.f;
            const float4* kr = (const float4*)(Ks + j * 64);
#pragma unroll
            for (int d4 = 0; d4 < 16; d4++) {
                float4 kk = kr[d4];
                s += qr[d4 * 4 + 0] * kk.x + qr[d4 * 4 + 1] * kk.y
                   + qr[d4 * 4 + 2] * kk.z + qr[d4 * 4 + 3] * kk.w;
            }
            s *= 0.125f;
            float mn = fmaxf(m, s);
            float corr = __expf(m - mn);
            float p = __expf(s - mn);
            lsum = lsum * corr + p;
            m = mn;
            const float4* vr = (const float4*)(Vs + j * 64);
#pragma unroll
            for (int d4 = 0; d4 < 16; d4++) {
                float4 vv = vr[d4];
                acc[d4 * 4 + 0] = acc[d4 * 4 + 0] * corr + p * vv.x;
                acc[d4 * 4 + 1] = acc[d4 * 4 + 1] * corr + p * vv.y;
                acc[d4 * 4 + 2] = acc[d4 * 4 + 2] * corr + p * vv.z;
                acc[d4 * 4 + 3] = acc[d4 * 4 + 3] * corr + p * vv.w;
            }
        }
    }
    float inv = 1.0f / lsum;
    __syncthreads();
#pragma unroll
    for (int d = 0; d < 64; d++) Qs[d][tid] = acc[d] * inv;
    __syncthreads();
    for (int e = tid; e < 256 * 64; e += 256) {
        int j = e >> 6, d = e & 63;
        o[(rowbase + j) * DD + colbase + d] = Qs[d][j];
    }
}

// ---------------- host launch ----------------
extern "C" void kernel_launch(void* const* d_in, const int* in_sizes, int n_in,
                              void* d_out, int out_size)
{
    const float* inp   = (const float*)d_in[0];
    const float* Wq_t  = (const float*)d_in[1];
    const float* Wk_t  = (const float*)d_in[2];
    const float* Wv_t  = (const float*)d_in[3];
    const float* Wo_t  = (const float*)d_in[4];
    const float* bo_t  = (const float*)d_in[5];
    const float* Wq_s  = (const float*)d_in[6];
    const float* Wk_s  = (const float*)d_in[7];
    const float* Wv_s  = (const float*)d_in[8];
    const float* Wo_s  = (const float*)d_in[9];
    const float* bo_s  = (const float*)d_in[10];
    const float* ln_ts = (const float*)d_in[11];
    const float* ln_tb = (const float*)d_in[12];
    const float* ln_ss = (const float*)d_in[13];
    const float* ln_sb = (const float*)d_in[14];
    const float* ln2s  = (const float*)d_in[15];
    const float* ln2b  = (const float*)d_in[16];
    const float* W1    = (const float*)d_in[17];
    const float* b1    = (const float*)d_in[18];
    const float* W2    = (const float*)d_in[19];
    const float* b2    = (const float*)d_in[20];
    float* out = (float*)d_out;

    cudaFuncSetAttribute(attn_space_kernel,
                         cudaFuncAttributeMaxDynamicSharedMemorySize, SPACE_SMEM);

    float *gx, *gq, *gk, *gv, *ga, *gf;
    cudaGetSymbolAddress((void**)&gx, g_x);
    cudaGetSymbolAddress((void**)&gq, g_q);
    cudaGetSymbolAddress((void**)&gk, g_k);
    cudaGetSymbolAddress((void**)&gv, g_v);
    cudaGetSymbolAddress((void**)&ga, g_att);
    cudaGetSymbolAddress((void**)&gf, g_ff);

    cudaMemcpyAsync(out, inp, (size_t)NTOK * DD * sizeof(float),
                    cudaMemcpyDeviceToDevice);

    dim3 gD(DD / 128, NTOK / 128);   // (6, 128)
    dim3 gF(FFW_ / 128, NTOK / 128); // (24, 128)

    for (int lyr = 0; lyr < NLAYER; lyr++) {
        size_t wo  = (size_t)lyr * DD * DD;
        size_t w1o = (size_t)lyr * DD * FFW_;
        size_t vo  = (size_t)lyr * DD;
        size_t fo  = (size_t)lyr * FFW_;

        // ---- time attention block ----
        ln_kernel<<<NTOK, 256>>>(out, ln_ts + vo, ln_tb + vo, gx);
        gemm_kernel<0><<<gD, 256>>>(gx, Wq_t + wo, nullptr, gq, DD, DD);
        gemm_kernel<0><<<gD, 256>>>(gx, Wk_t + wo, nullptr, gk, DD, DD);
        gemm_kernel<0><<<gD, 256>>>(gx, Wv_t + wo, nullptr, gv, DD, DD);
        attn_time_kernel<<<dim3(NB * LL, HH), 32>>>(gq, gk, gv, ga);
        gemm_kernel<2><<<gD, 256>>>(ga, Wo_t + wo, bo_t + vo, out, DD, DD);

        // ---- space attention block ----
        ln_kernel<<<NTOK, 256>>>(out, ln_ss + vo, ln_sb + vo, gx);
        gemm_kernel<0><<<gD, 256>>>(gx, Wq_s + wo, nullptr, gq, DD, DD);
        gemm_kernel<0><<<gD, 256>>>(gx, Wk_s + wo, nullptr, gk, DD, DD);
        gemm_kernel<0><<<gD, 256>>>(gx, Wv_s + wo, nullptr, gv, DD, DD);
        attn_space_kernel<<<NB * TT * HH, 256, SPACE_SMEM>>>(gq, gk, gv, ga);
        gemm_kernel<2><<<gD, 256>>>(ga, Wo_s + wo, bo_s + vo, out, DD, DD);

        // ---- FFN block ----
        ln_kernel<<<NTOK, 256>>>(out, ln2s + vo, ln2b + vo, gx);
        gemm_kernel<1><<<gF, 256>>>(gx, W1 + w1o, b1 + fo, gf, DD, FFW_);
        gemm_kernel<2><<<gD, 256>>>(gf, W2 + w1o, b2 + vo, out, FFW_, DD);
    }
}

// round 3
// speedup vs baseline: 1.7748x; 1.7748x over previous
#include <cuda_runtime.h>
#include <cuda_bf16.h>
#include <cstdint>
#include <math.h>

#define NB 2
#define TT 32
#define LL 256
#define DD 768
#define HH 12
#define HD 64
#define FFW_ 3072
#define NLAYER 4
#define NTOK (NB*TT*LL)   // 16384

typedef __nv_bfloat16 bf16;

// ---------------- scratch (device globals, no allocation) ----------------
__device__ float g_q[(size_t)NTOK*DD];
__device__ float g_k[(size_t)NTOK*DD];
__device__ float g_v[(size_t)NTOK*DD];
__device__ bf16  g_xh[(size_t)NTOK*DD];
__device__ bf16  g_xl[(size_t)NTOK*DD];
__device__ bf16  g_ah[(size_t)NTOK*DD];
__device__ bf16  g_al[(size_t)NTOK*DD];
__device__ bf16  g_ffh[(size_t)NTOK*FFW_];
__device__ bf16  g_ffl[(size_t)NTOK*FFW_];

// transposed split weights [N,K] per layer
#define WT_QKV_T 0
#define WT_QKV_S 1769472
#define WT_WO_T  3538944
#define WT_WO_S  4128768
#define WT_W1    4718592
#define WT_W2    7077888
#define WT_LAYER 9437184
__device__ bf16 g_wth[(size_t)WT_LAYER*NLAYER];
__device__ bf16 g_wtl[(size_t)WT_LAYER*NLAYER];

// ---------------- helpers ----------------
__device__ __forceinline__ uint32_t smem_u32(const void* p) {
    uint32_t a;
    asm("{ .reg .u64 t; cvta.to.shared.u64 t, %1; cvt.u32.u64 %0, t; }" : "=r"(a) : "l"(p));
    return a;
}
__device__ __forceinline__ void cp16(uint32_t s, const void* g) {
    asm volatile("cp.async.cg.shared.global [%0], [%1], 16;" :: "r"(s), "l"(g));
}
__device__ __forceinline__ void cp_commit() {
    asm volatile("cp.async.commit_group;" ::: "memory");
}
__device__ __forceinline__ void cp_wait1() {
    asm volatile("cp.async.wait_group 1;" ::: "memory");
}
__device__ __forceinline__ void ldmA(uint32_t* r, uint32_t addr) {
    asm volatile("ldmatrix.sync.aligned.m8n8.x4.shared.b16 {%0,%1,%2,%3}, [%4];"
                 : "=r"(r[0]), "=r"(r[1]), "=r"(r[2]), "=r"(r[3]) : "r"(addr));
}
__device__ __forceinline__ void ldmB(uint32_t* r, uint32_t addr) {
    asm volatile("ldmatrix.sync.aligned.m8n8.x2.shared.b16 {%0,%1}, [%2];"
                 : "=r"(r[0]), "=r"(r[1]) : "r"(addr));
}
__device__ __forceinline__ void mma16816(float* c, const uint32_t* a, const uint32_t* b) {
    asm volatile(
        "mma.sync.aligned.m16n8k16.row.col.f32.bf16.bf16.f32 "
        "{%0,%1,%2,%3}, {%4,%5,%6,%7}, {%8,%9}, {%0,%1,%2,%3};"
        : "+f"(c[0]), "+f"(c[1]), "+f"(c[2]), "+f"(c[3])
        : "r"(a[0]), "r"(a[1]), "r"(a[2]), "r"(a[3]), "r"(b[0]), "r"(b[1]));
}
__device__ __forceinline__ void split_bf16(float v, bf16& h, bf16& l) {
    h = __float2bfloat16(v);
    l = __float2bfloat16(v - __bfloat162float(h));
}
__device__ __forceinline__ float gelu_tanh(float x) {
    float x3 = x * x * x;
    return 0.5f * x * (1.0f + tanhf(0.7978845608028654f * (x + 0.044715f * x3)));
}

// ---------------- weight convert + transpose + bf16 split ----------------
__global__ void convT(const float* __restrict__ W, bf16* __restrict__ th,
                      bf16* __restrict__ tl, int K, int N)
{
    __shared__ float t[32][33];
    int n0 = blockIdx.x * 32, k0 = blockIdx.y * 32;
    int tx = threadIdx.x, ty = threadIdx.y; // (32,8)
#pragma unroll
    for (int r = 0; r < 4; r++) {
        int k = k0 + ty + r * 8;
        t[ty + r * 8][tx] = W[(size_t)k * N + n0 + tx];
    }
    __syncthreads();
#pragma unroll
    for (int r = 0; r < 4; r++) {
        int n = n0 + ty + r * 8;
        float v = t[tx][ty + r * 8];
        bf16 h, l; split_bf16(v, h, l);
        th[(size_t)n * K + k0 + tx] = h;
        tl[(size_t)n * K + k0 + tx] = l;
    }
}

// ---------------- LayerNorm -> split bf16 ----------------
__global__ void ln_kernel(const float* __restrict__ h, const float* __restrict__ sc,
                          const float* __restrict__ bi,
                          bf16* __restrict__ xh, bf16* __restrict__ xl)
{
    int row = blockIdx.x;
    const float* hr = h + (size_t)row * DD;
    int tid = threadIdx.x;
    float v0 = hr[tid], v1 = hr[tid + 256], v2 = hr[tid + 512];
    __shared__ float red[256];
    red[tid] = v0 + v1 + v2;
    __syncthreads();
    for (int o = 128; o > 0; o >>= 1) {
        if (tid < o) red[tid] += red[tid + o];
        __syncthreads();
    }
    float mean = red[0] * (1.0f / DD);
    __syncthreads();
    float d0 = v0 - mean, d1 = v1 - mean, d2 = v2 - mean;
    red[tid] = d0 * d0 + d1 * d1 + d2 * d2;
    __syncthreads();
    for (int o = 128; o > 0; o >>= 1) {
        if (tid < o) red[tid] += red[tid + o];
        __syncthreads();
    }
    float rstd = rsqrtf(red[0] * (1.0f / DD) + 1e-5f);
    size_t base = (size_t)row * DD;
    float y0 = d0 * rstd * sc[tid]       + bi[tid];
    float y1 = d1 * rstd * sc[tid + 256] + bi[tid + 256];
    float y2 = d2 * rstd * sc[tid + 512] + bi[tid + 512];
    bf16 hh, ll;
    split_bf16(y0, hh, ll); xh[base + tid] = hh;       xl[base + tid] = ll;
    split_bf16(y1, hh, ll); xh[base + tid + 256] = hh; xl[base + tid + 256] = ll;
    split_bf16(y2, hh, ll); xh[base + tid + 512] = hh; xl[base + tid + 512] = ll;
}

// ---------------- HMMA GEMM: C[M,Nc] = A[M,Kd] @ B[Nc,Kd]^T ----------------
// block 128x128, 3-stage cp.async, warp tile 64x32, bf16x3 split fp32 accum.
// smem stage layout (pitch 40 bf16 = 80B per 32-col row):
//   Ah @ 0, Al @ 10240, Bh @ 20480, Bl @ 30720   (stage = 40960 B, 3 stages)
#define STAGEB 40960
#define GSMEM  (3*STAGEB)   // 122880

template <int EPI>
__global__ void __launch_bounds__(256) mma_gemm(
    const bf16* __restrict__ Ah, const bf16* __restrict__ Al,
    const bf16* __restrict__ Bh, const bf16* __restrict__ Bl,
    const float* __restrict__ bias,
    float* __restrict__ C0, float* __restrict__ C1, float* __restrict__ C2,
    bf16* __restrict__ Oh, bf16* __restrict__ Ol,
    int Kd, int Nc)
{
    extern __shared__ char sm[];
    const uint32_t sb = smem_u32(sm);
    const int tid = threadIdx.x;
    const int lane = tid & 31, wid = tid >> 5;
    const int wm = wid & 1, wn = wid >> 1;   // warp tile: rows wm*64, cols wn*32
    const int bm = blockIdx.y * 128;
    const int bn = blockIdx.x * 128;

    const bf16* pAh0 = Ah + (size_t)bm * Kd;
    const bf16* pAl0 = Al + (size_t)bm * Kd;
    const bf16* pBh0 = Bh + (size_t)bn * Kd;
    const bf16* pBl0 = Bl + (size_t)bn * Kd;

    const int r_ld = tid >> 2;          // 0..63 (+64 on second iter)
    const int c_ld = tid & 3;           // 16B chunk
    const uint32_t so_ld = (uint32_t)(r_ld * 80 + c_ld * 16);

    float acc[4][4][4];
#pragma unroll
    for (int mi = 0; mi < 4; mi++)
#pragma unroll
        for (int ni = 0; ni < 4; ni++)
#pragma unroll
            for (int e = 0; e < 4; e++) acc[mi][ni][e] = 0.f;

    const uint32_t a_off = (uint32_t)((wm * 64 + (lane & 15)) * 80 + (lane >> 4) * 16);
    const uint32_t b_off = (uint32_t)((wn * 32 + (lane & 7)) * 80 + ((lane >> 3) & 1) * 16);

    const int KT = Kd >> 5;   // k32 chunks

    // prologue: load stages 0,1
#pragma unroll
    for (int s = 0; s < 2; s++) {
        int k0 = s * 32;
#pragma unroll
        for (int i = 0; i < 2; i++) {
            int r = r_ld + i * 64;
            uint32_t so = sb + s * STAGEB + so_ld + (uint32_t)(i * 64 * 80);
            size_t gA = (size_t)r * Kd + k0 + c_ld * 8;
            cp16(so,         pAh0 + gA);
            cp16(so + 10240, pAl0 + gA);
            cp16(so + 20480, pBh0 + gA);
            cp16(so + 30720, pBl0 + gA);
        }
        cp_commit();
    }

    for (int kt = 0; kt < KT; kt++) {
        cp_wait1();
        __syncthreads();
        int kpre = kt + 2;
        if (kpre < KT) {
            int s = kpre % 3, k0 = kpre * 32;
#pragma unroll
            for (int i = 0; i < 2; i++) {
                int r = r_ld + i * 64;
                uint32_t so = sb + s * STAGEB + so_ld + (uint32_t)(i * 64 * 80);
                size_t gA = (size_t)r * Kd + k0 + c_ld * 8;
                cp16(so,         pAh0 + gA);
                cp16(so + 10240, pAl0 + gA);
                cp16(so + 20480, pBh0 + gA);
                cp16(so + 30720, pBl0 + gA);
            }
        }
        cp_commit();

        uint32_t st = sb + (kt % 3) * STAGEB;
#pragma unroll
        for (int kk = 0; kk < 2; kk++) {
            uint32_t ka = st + a_off + kk * 32;
            uint32_t kb = st + b_off + kk * 32;
            uint32_t ah[4][4], al[4][4], bh[4][2], bl[4][2];
#pragma unroll
            for (int mi = 0; mi < 4; mi++) {
                ldmA(ah[mi], ka + mi * 1280);           // 16 rows * 80B
                ldmA(al[mi], ka + 10240 + mi * 1280);
            }
#pragma unroll
            for (int ni = 0; ni < 4; ni++) {
                ldmB(bh[ni], kb + 20480 + ni * 640);    // 8 rows * 80B
                ldmB(bl[ni], kb + 30720 + ni * 640);
            }
#pragma unroll
            for (int mi = 0; mi < 4; mi++)
#pragma unroll
                for (int ni = 0; ni < 4; ni++) {
                    mma16816(acc[mi][ni], ah[mi], bh[ni]);
                    mma16816(acc[mi][ni], al[mi], bh[ni]);
                    mma16816(acc[mi][ni], ah[mi], bl[ni]);
                }
        }
        __syncthreads();
    }

    // stage C through smem for coalesced epilogue
    float* Cs = (float*)sm;   // [128][132]
    const int g = lane >> 2, t4 = lane & 3;
#pragma unroll
    for (int mi = 0; mi < 4; mi++)
#pragma unroll
        for (int ni = 0; ni < 4; ni++) {
            int row = wm * 64 + mi * 16 + g;
            int col = wn * 32 + ni * 8 + t4 * 2;
            Cs[row * 132 + col]           = acc[mi][ni][0];
            Cs[row * 132 + col + 1]       = acc[mi][ni][1];
            Cs[(row + 8) * 132 + col]     = acc[mi][ni][2];
            Cs[(row + 8) * 132 + col + 1] = acc[mi][ni][3];
        }
    __syncthreads();

    const int col = tid & 127;
    const int rof = tid >> 7;   // 0/1
    if (EPI == 0) {
        float* dst; int nb = bn;
        if (nb < 768) dst = C0;
        else if (nb < 1536) { dst = C1; nb -= 768; }
        else { dst = C2; nb -= 1536; }
#pragma unroll 4
        for (int it = 0; it < 64; it++) {
            int r = it * 2 + rof;
            dst[(size_t)(bm + r) * 768 + nb + col] = Cs[r * 132 + col];
        }
    } else if (EPI == 1) {
        float bb = bias[bn + col];
#pragma unroll 4
        for (int it = 0; it < 64; it++) {
            int r = it * 2 + rof;
            float gl = gelu_tanh(Cs[r * 132 + col] + bb);
            bf16 h, l; split_bf16(gl, h, l);
            size_t o = (size_t)(bm + r) * Nc + bn + col;
            Oh[o] = h; Ol[o] = l;
        }
    } else {
        float bb = bias[bn + col];
#pragma unroll 4
        for (int it = 0; it < 64; it++) {
            int r = it * 2 + rof;
            size_t o = (size_t)(bm + r) * Nc + bn + col;
            C0[o] += Cs[r * 132 + col] + bb;
        }
    }
}

// ---------------- Time attention (T=32) ----------------
__global__ void __launch_bounds__(32) attn_time_kernel(
    const float* __restrict__ q, const float* __restrict__ k,
    const float* __restrict__ v, bf16* __restrict__ oh, bf16* __restrict__ ol)
{
    __shared__ float Ks[32][64];
    __shared__ float Vs[32][64];
    __shared__ float Qs[64][33];
    int bl = blockIdx.x;
    int h = blockIdx.y;
    int b = bl / LL, l = bl % LL;
    int tid = threadIdx.x;
    size_t colbase = (size_t)h * HD;

    for (int e = tid; e < 32 * 64; e += 32) {
        int j = e >> 6, d = e & 63;
        size_t off = ((size_t)(b * TT + j) * LL + l) * DD + colbase + d;
        Ks[j][d] = k[off];
        Vs[j][d] = v[off];
        Qs[d][j] = q[off];
    }
    __syncwarp();

    float qr[64];
#pragma unroll
    for (int d = 0; d < 64; d++) qr[d] = Qs[d][tid];

    float sc_[32];
#pragma unroll 4
    for (int j = 0; j < 32; j++) {
        float s = 0.f;
        const float4* kr = (const float4*)Ks[j];
#pragma unroll
        for (int d4 = 0; d4 < 16; d4++) {
            float4 kk = kr[d4];
            s += qr[d4 * 4 + 0] * kk.x + qr[d4 * 4 + 1] * kk.y
               + qr[d4 * 4 + 2] * kk.z + qr[d4 * 4 + 3] * kk.w;
        }
        sc_[j] = s * 0.125f;
    }
    float m = sc_[0];
#pragma unroll
    for (int j = 1; j < 32; j++) m = fmaxf(m, sc_[j]);
    float lsum = 0.f;
#pragma unroll
    for (int j = 0; j < 32; j++) { sc_[j] = __expf(sc_[j] - m); lsum += sc_[j]; }
    float inv = 1.0f / lsum;

#pragma unroll
    for (int d4 = 0; d4 < 16; d4++) {
        float ax = 0.f, ay = 0.f, az = 0.f, aw = 0.f;
#pragma unroll
        for (int j = 0; j < 32; j++) {
            float4 vv = ((const float4*)Vs[j])[d4];
            float w = sc_[j];
            ax += w * vv.x; ay += w * vv.y; az += w * vv.z; aw += w * vv.w;
        }
        Qs[d4 * 4 + 0][tid] = ax * inv;
        Qs[d4 * 4 + 1][tid] = ay * inv;
        Qs[d4 * 4 + 2][tid] = az * inv;
        Qs[d4 * 4 + 3][tid] = aw * inv;
    }
    __syncwarp();
    for (int e = tid; e < 32 * 64; e += 32) {
        int j = e >> 6, d = e & 63;
        size_t off = ((size_t)(b * TT + j) * LL + l) * DD + colbase + d;
        bf16 h2, l2; split_bf16(Qs[d][j], h2, l2);
        oh[off] = h2; ol[off] = l2;
    }
}

// ---------------- Space attention (L=256) ----------------
#define SPACE_SMEM ((64 * 257 + 64 * 64 + 64 * 64) * 4)
__global__ void __launch_bounds__(256) attn_space_kernel(
    const float* __restrict__ q, const float* __restrict__ k,
    const float* __restrict__ v, bf16* __restrict__ oh, bf16* __restrict__ ol)
{
    extern __shared__ float smf[];
    float(*Qs)[257] = (float(*)[257])smf;
    float* Ks = smf + 64 * 257;
    float* Vs = Ks + 64 * 64;
    int gid = blockIdx.x;
    int h = gid % HH;
    int bt = gid / HH;
    int tid = threadIdx.x;
    size_t rowbase = (size_t)bt * LL;
    size_t colbase = (size_t)h * HD;

    for (int e = tid; e < 256 * 64; e += 256) {
        int j = e >> 6, d = e & 63;
        Qs[d][j] = q[(rowbase + j) * DD + colbase + d];
    }
    __syncthreads();

    float qr[64];
#pragma unroll
    for (int d = 0; d < 64; d++) qr[d] = Qs[d][tid];

    float m = -1e30f, lsum = 0.f;
    float acc[64];
#pragma unroll
    for (int d = 0; d < 64; d++) acc[d] = 0.f;

    for (int c0 = 0; c0 < LL; c0 += 64) {
        __syncthreads();
        for (int e = tid; e < 64 * 64; e += 256) {
            int j = e >> 6, d = e & 63;
            size_t off = (rowbase + c0 + j) * DD + colbase + d;
            Ks[e] = k[off];
            Vs[e] = v[off];
        }
        __syncthreads();
        for (int j = 0; j < 64; j++) {
            float s = 0.f;
            const float4* kr = (const float4*)(Ks + j * 64);
#pragma unroll
            for (int d4 = 0; d4 < 16; d4++) {
                float4 kk = kr[d4];
                s += qr[d4 * 4 + 0] * kk.x + qr[d4 * 4 + 1] * kk.y
                   + qr[d4 * 4 + 2] * kk.z + qr[d4 * 4 + 3] * kk.w;
            }
            s *= 0.125f;
            float mn = fmaxf(m, s);
            float corr = __expf(m - mn);
            float p = __expf(s - mn);
            lsum = lsum * corr + p;
            m = mn;
            const float4* vr = (const float4*)(Vs + j * 64);
#pragma unroll
            for (int d4 = 0; d4 < 16; d4++) {
                float4 vv = vr[d4];
                acc[d4 * 4 + 0] = acc[d4 * 4 + 0] * corr + p * vv.x;
                acc[d4 * 4 + 1] = acc[d4 * 4 + 1] * corr + p * vv.y;
                acc[d4 * 4 + 2] = acc[d4 * 4 + 2] * corr + p * vv.z;
                acc[d4 * 4 + 3] = acc[d4 * 4 + 3] * corr + p * vv.w;
            }
        }
    }
    float inv = 1.0f / lsum;
    __syncthreads();
#pragma unroll
    for (int d = 0; d < 64; d++) Qs[d][tid] = acc[d] * inv;
    __syncthreads();
    for (int e = tid; e < 256 * 64; e += 256) {
        int j = e >> 6, d = e & 63;
        size_t off = (rowbase + j) * DD + colbase + d;
        bf16 h2, l2; split_bf16(Qs[d][j], h2, l2);
        oh[off] = h2; ol[off] = l2;
    }
}

// ---------------- host launch ----------------
extern "C" void kernel_launch(void* const* d_in, const int* in_sizes, int n_in,
                              void* d_out, int out_size)
{
    const float* inp   = (const float*)d_in[0];
    const float* Wq_t  = (const float*)d_in[1];
    const float* Wk_t  = (const float*)d_in[2];
    const float* Wv_t  = (const float*)d_in[3];
    const float* Wo_t  = (const float*)d_in[4];
    const float* bo_t  = (const float*)d_in[5];
    const float* Wq_s  = (const float*)d_in[6];
    const float* Wk_s  = (const float*)d_in[7];
    const float* Wv_s  = (const float*)d_in[8];
    const float* Wo_s  = (const float*)d_in[9];
    const float* bo_s  = (const float*)d_in[10];
    const float* ln_ts = (const float*)d_in[11];
    const float* ln_tb = (const float*)d_in[12];
    const float* ln_ss = (const float*)d_in[13];
    const float* ln_sb = (const float*)d_in[14];
    const float* ln2s  = (const float*)d_in[15];
    const float* ln2b  = (const float*)d_in[16];
    const float* W1    = (const float*)d_in[17];
    const float* b1    = (const float*)d_in[18];
    const float* W2    = (const float*)d_in[19];
    const float* b2    = (const float*)d_in[20];
    float* out = (float*)d_out;

    cudaFuncSetAttribute(attn_space_kernel,
                         cudaFuncAttributeMaxDynamicSharedMemorySize, SPACE_SMEM);
    cudaFuncSetAttribute(mma_gemm<0>, cudaFuncAttributeMaxDynamicSharedMemorySize, GSMEM);
    cudaFuncSetAttribute(mma_gemm<1>, cudaFuncAttributeMaxDynamicSharedMemorySize, GSMEM);
    cudaFuncSetAttribute(mma_gemm<2>, cudaFuncAttributeMaxDynamicSharedMemorySize, GSMEM);

    float *gq, *gk, *gv;
    bf16 *gxh, *gxl, *gah, *gal, *gfh, *gfl, *wth, *wtl;
    cudaGetSymbolAddress((void**)&gq, g_q);
    cudaGetSymbolAddress((void**)&gk, g_k);
    cudaGetSymbolAddress((void**)&gv, g_v);
    cudaGetSymbolAddress((void**)&gxh, g_xh);
    cudaGetSymbolAddress((void**)&gxl, g_xl);
    cudaGetSymbolAddress((void**)&gah, g_ah);
    cudaGetSymbolAddress((void**)&gal, g_al);
    cudaGetSymbolAddress((void**)&gfh, g_ffh);
    cudaGetSymbolAddress((void**)&gfl, g_ffl);
    cudaGetSymbolAddress((void**)&wth, g_wth);
    cudaGetSymbolAddress((void**)&wtl, g_wtl);

    cudaMemcpyAsync(out, inp, (size_t)NTOK * DD * sizeof(float),
                    cudaMemcpyDeviceToDevice);

    // convert + transpose + split all weights
    dim3 cb(32, 8);
    for (int lyr = 0; lyr < NLAYER; lyr++) {
        size_t wo  = (size_t)lyr * DD * DD;
        size_t w1o = (size_t)lyr * DD * FFW_;
        size_t base = (size_t)lyr * WT_LAYER;
        dim3 gdd(DD / 32, DD / 32);
        convT<<<gdd, cb>>>(Wq_t + wo, wth + base + WT_QKV_T,           wtl + base + WT_QKV_T,           DD, DD);
        convT<<<gdd, cb>>>(Wk_t + wo, wth + base + WT_QKV_T + 589824,  wtl + base + WT_QKV_T + 589824,  DD, DD);
        convT<<<gdd, cb>>>(Wv_t + wo, wth + base + WT_QKV_T + 1179648, wtl + base + WT_QKV_T + 1179648, DD, DD);
        convT<<<gdd, cb>>>(Wq_s + wo, wth + base + WT_QKV_S,           wtl + base + WT_QKV_S,           DD, DD);
        convT<<<gdd, cb>>>(Wk_s + wo, wth + base + WT_QKV_S + 589824,  wtl + base + WT_QKV_S + 589824,  DD, DD);
        convT<<<gdd, cb>>>(Wv_s + wo, wth + base + WT_QKV_S + 1179648, wtl + base + WT_QKV_S + 1179648, DD, DD);
        convT<<<gdd, cb>>>(Wo_t + wo, wth + base + WT_WO_T, wtl + base + WT_WO_T, DD, DD);
        convT<<<gdd, cb>>>(Wo_s + wo, wth + base + WT_WO_S, wtl + base + WT_WO_S, DD, DD);
        convT<<<dim3(FFW_ / 32, DD / 32), cb>>>(W1 + w1o, wth + base + WT_W1, wtl + base + WT_W1, DD, FFW_);
        convT<<<dim3(DD / 32, FFW_ / 32), cb>>>(W2 + w1o, wth + base + WT_W2, wtl + base + WT_W2, FFW_, DD);
    }

    dim3 gQKV(18, 128), gO(6, 128), gF1(24, 128), gF2(6, 128);

    for (int lyr = 0; lyr < NLAYER; lyr++) {
        size_t vo = (size_t)lyr * DD;
        size_t fo = (size_t)lyr * FFW_;
        size_t base = (size_t)lyr * WT_LAYER;

        // ---- time attention block ----
        ln_kernel<<<NTOK, 256>>>(out, ln_ts + vo, ln_tb + vo, gxh, gxl);
        mma_gemm<0><<<gQKV, 256, GSMEM>>>(gxh, gxl,
            wth + base + WT_QKV_T, wtl + base + WT_QKV_T,
            nullptr, gq, gk, gv, nullptr, nullptr, DD, 2304);
        attn_time_kernel<<<dim3(NB * LL, HH), 32>>>(gq, gk, gv, gah, gal);
        mma_gemm<2><<<gO, 256, GSMEM>>>(gah, gal,
            wth + base + WT_WO_T, wtl + base + WT_WO_T,
            bo_t + vo, out, nullptr, nullptr, nullptr, nullptr, DD, DD);

        // ---- space attention block ----
        ln_kernel<<<NTOK, 256>>>(out, ln_ss + vo, ln_sb + vo, gxh, gxl);
        mma_gemm<0><<<gQKV, 256, GSMEM>>>(gxh, gxl,
            wth + base + WT_QKV_S, wtl + base + WT_QKV_S,
            nullptr, gq, gk, gv, nullptr, nullptr, DD, 2304);
        attn_space_kernel<<<NB * TT * HH, 256, SPACE_SMEM>>>(gq, gk, gv, gah, gal);
        mma_gemm<2><<<gO, 256, GSMEM>>>(gah, gal,
            wth + base + WT_WO_S, wtl + base + WT_WO_S,
            bo_s + vo, out, nullptr, nullptr, nullptr, nullptr, DD, DD);

        // ---- FFN block ----
        ln_kernel<<<NTOK, 256>>>(out, ln2s + vo, ln2b + vo, gxh, gxl);
        mma_gemm<1><<<gF1, 256, GSMEM>>>(gxh, gxl,
            wth + base + WT_W1, wtl + base + WT_W1,
            b1 + fo, nullptr, nullptr, nullptr, gfh, gfl, DD, FFW_);
        mma_gemm<2><<<gF2, 256, GSMEM>>>(gfh, gfl,
            wth + base + WT_W2, wtl + base + WT_W2,
            b2 + vo, out, nullptr, nullptr, nullptr, nullptr, FFW_, DD);
    }
}

// round 6
// speedup vs baseline: 2.3382x; 1.3174x over previous
#include <cuda_runtime.h>
#include <cuda_bf16.h>
#include <cstdint>
#include <math.h>

#define NB 2
#define TT 32
#define LL 256
#define DD 768
#define HH 12
#define HD 64
#define FFW_ 3072
#define NLAYER 4
#define NTOK (NB*TT*LL)   // 16384

typedef __nv_bfloat16 bf16;

#if defined(__CUDA_ARCH_FEAT_SM103_ALL) || defined(__CUDA_ARCH_FEAT_SM100_ALL) || defined(__CUDA_ARCH_FEAT_SM101_ALL)
#define HAS_TCGEN05 1
#else
#define HAS_TCGEN05 0
#endif

// ---------------- scratch (device globals, no allocation) ----------------
__device__ float g_q[(size_t)NTOK*DD];
__device__ float g_k[(size_t)NTOK*DD];
__device__ float g_v[(size_t)NTOK*DD];
__device__ bf16  g_xh[(size_t)NTOK*DD];
__device__ bf16  g_xl[(size_t)NTOK*DD];
__device__ bf16  g_ah[(size_t)NTOK*DD];
__device__ bf16  g_al[(size_t)NTOK*DD];
__device__ bf16  g_ffh[(size_t)NTOK*FFW_];
__device__ bf16  g_ffl[(size_t)NTOK*FFW_];

// transposed split weights [N,K] per layer
#define WT_QKV_T 0
#define WT_QKV_S 1769472
#define WT_WO_T  3538944
#define WT_WO_S  4128768
#define WT_W1    4718592
#define WT_W2    7077888
#define WT_LAYER 9437184
__device__ bf16 g_wth[(size_t)WT_LAYER*NLAYER];
__device__ bf16 g_wtl[(size_t)WT_LAYER*NLAYER];

// ---------------- helpers ----------------
__device__ __forceinline__ uint32_t smem_u32(const void* p) {
    uint32_t a;
    asm("{ .reg .u64 t; cvta.to.shared.u64 t, %1; cvt.u32.u64 %0, t; }" : "=r"(a) : "l"(p));
    return a;
}
__device__ __forceinline__ void split_bf16(float v, bf16& h, bf16& l) {
    h = __float2bfloat16(v);
    l = __float2bfloat16(v - __bfloat162float(h));
}
__device__ __forceinline__ float gelu_tanh(float x) {
    float x3 = x * x * x;
    return 0.5f * x * (1.0f + tanhf(0.7978845608028654f * (x + 0.044715f * x3)));
}

#if HAS_TCGEN05
__device__ __forceinline__ uint32_t elect_one() {
    uint32_t p;
    asm volatile("{\n\t.reg .pred p;\n\telect.sync _|p, 0xFFFFFFFF;\n\tselp.b32 %0, 1, 0, p;\n\t}" : "=r"(p));
    return p;
}
__device__ __forceinline__ void mbar_init(uint32_t a, uint32_t c) {
    asm volatile("mbarrier.init.shared.b64 [%0], %1;" :: "r"(a), "r"(c) : "memory");
}
__device__ __forceinline__ void mbar_inval(uint32_t a) {
    asm volatile("mbarrier.inval.shared.b64 [%0];" :: "r"(a) : "memory");
}
__device__ __forceinline__ void mbar_wait(uint32_t a, uint32_t ph) {
    uint32_t done = 0;
    while (!done) {
        asm volatile(
            "{\n\t.reg .pred p;\n\t"
            "mbarrier.try_wait.parity.acquire.cta.shared::cta.b64 p, [%1], %2, 0x989680;\n\t"
            "selp.b32 %0, 1, 0, p;\n\t}"
            : "=r"(done) : "r"(a), "r"(ph) : "memory");
    }
}
__device__ __forceinline__ void tm_alloc(uint32_t dst, uint32_t n) {
    asm volatile("tcgen05.alloc.cta_group::1.sync.aligned.shared::cta.b32 [%0], %1;"
                 :: "r"(dst), "r"(n) : "memory");
}
__device__ __forceinline__ void tm_relinq() {
    asm volatile("tcgen05.relinquish_alloc_permit.cta_group::1.sync.aligned;");
}
__device__ __forceinline__ void tm_dealloc(uint32_t t, uint32_t n) {
    asm volatile("tcgen05.dealloc.cta_group::1.sync.aligned.b32 %0, %1;" :: "r"(t), "r"(n));
}
__device__ __forceinline__ void tm_commit(uint32_t mbar) {
    asm volatile("tcgen05.commit.cta_group::1.mbarrier::arrive::one.shared::cluster.b64 [%0];"
                 :: "r"(mbar) : "memory");
}
__device__ __forceinline__ void mma_f16_ss(uint32_t d, uint64_t a, uint64_t b,
                                           uint32_t idesc, uint32_t en) {
    asm volatile(
        "{\n\t.reg .pred p;\n\tsetp.ne.u32 p, %4, 0;\n\t"
        "tcgen05.mma.cta_group::1.kind::f16 [%0], %1, %2, %3, {%5, %5, %5, %5}, p;\n\t}"
        :: "r"(d), "l"(a), "l"(b), "r"(idesc), "r"(en), "r"(0u) : "memory");
}
__device__ __forceinline__ uint64_t mkdesc(uint32_t addr) {
    return (((uint64_t)2 << 61) | ((uint64_t)1 << 46) | ((uint64_t)64 << 32) |
            ((uint64_t)1 << 16)) | (uint64_t)((addr >> 4) & 0x3FFF);
}
#define LDTM_X32(r, a) \
    asm volatile( \
        "tcgen05.ld.sync.aligned.32x32b.x32.b32 " \
        "{%0, %1, %2, %3, %4, %5, %6, %7, " \
        " %8, %9, %10, %11, %12, %13, %14, %15, " \
        " %16, %17, %18, %19, %20, %21, %22, %23, " \
        " %24, %25, %26, %27, %28, %29, %30, %31}, [%32];" \
        : "=r"((r)[0]),  "=r"((r)[1]),  "=r"((r)[2]),  "=r"((r)[3]), \
          "=r"((r)[4]),  "=r"((r)[5]),  "=r"((r)[6]),  "=r"((r)[7]), \
          "=r"((r)[8]),  "=r"((r)[9]),  "=r"((r)[10]), "=r"((r)[11]), \
          "=r"((r)[12]), "=r"((r)[13]), "=r"((r)[14]), "=r"((r)[15]), \
          "=r"((r)[16]), "=r"((r)[17]), "=r"((r)[18]), "=r"((r)[19]), \
          "=r"((r)[20]), "=r"((r)[21]), "=r"((r)[22]), "=r"((r)[23]), \
          "=r"((r)[24]), "=r"((r)[25]), "=r"((r)[26]), "=r"((r)[27]), \
          "=r"((r)[28]), "=r"((r)[29]), "=r"((r)[30]), "=r"((r)[31]) \
        : "r"(a))
#endif

// ---------------- weight convert + transpose + bf16 split ----------------
__global__ void convT(const float* __restrict__ W, bf16* __restrict__ th,
                      bf16* __restrict__ tl, int K, int N)
{
    __shared__ float t[32][33];
    int n0 = blockIdx.x * 32, k0 = blockIdx.y * 32;
    int tx = threadIdx.x, ty = threadIdx.y; // (32,8)
#pragma unroll
    for (int r = 0; r < 4; r++) {
        int k = k0 + ty + r * 8;
        t[ty + r * 8][tx] = W[(size_t)k * N + n0 + tx];
    }
    __syncthreads();
#pragma unroll
    for (int r = 0; r < 4; r++) {
        int n = n0 + ty + r * 8;
        float v = t[tx][ty + r * 8];
        bf16 h, l; split_bf16(v, h, l);
        th[(size_t)n * K + k0 + tx] = h;
        tl[(size_t)n * K + k0 + tx] = l;
    }
}

// ---------------- LayerNorm -> split bf16 ----------------
__global__ void ln_kernel(const float* __restrict__ h, const float* __restrict__ sc,
                          const float* __restrict__ bi,
                          bf16* __restrict__ xh, bf16* __restrict__ xl)
{
    int row = blockIdx.x;
    const float* hr = h + (size_t)row * DD;
    int tid = threadIdx.x;
    float v0 = hr[tid], v1 = hr[tid + 256], v2 = hr[tid + 512];
    __shared__ float red[256];
    red[tid] = v0 + v1 + v2;
    __syncthreads();
    for (int o = 128; o > 0; o >>= 1) {
        if (tid < o) red[tid] += red[tid + o];
        __syncthreads();
    }
    float mean = red[0] * (1.0f / DD);
    __syncthreads();
    float d0 = v0 - mean, d1 = v1 - mean, d2 = v2 - mean;
    red[tid] = d0 * d0 + d1 * d1 + d2 * d2;
    __syncthreads();
    for (int o = 128; o > 0; o >>= 1) {
        if (tid < o) red[tid] += red[tid + o];
        __syncthreads();
    }
    float rstd = rsqrtf(red[0] * (1.0f / DD) + 1e-5f);
    size_t base = (size_t)row * DD;
    float y0 = d0 * rstd * sc[tid]       + bi[tid];
    float y1 = d1 * rstd * sc[tid + 256] + bi[tid + 256];
    float y2 = d2 * rstd * sc[tid + 512] + bi[tid + 512];
    bf16 hh, ll;
    split_bf16(y0, hh, ll); xh[base + tid] = hh;       xl[base + tid] = ll;
    split_bf16(y1, hh, ll); xh[base + tid + 256] = hh; xl[base + tid + 256] = ll;
    split_bf16(y2, hh, ll); xh[base + tid + 512] = hh; xl[base + tid + 512] = ll;
}

// ---------------- tcgen05 GEMM: C[M,Nc] = A[M,Kd] @ B[Nc,Kd]^T ----------------
// bf16x3 split: Ah*Bh + Al*Bh + Ah*Bl, fp32 accum in TMEM.
// Tile 128x256, double-buffered 96KB stages.
// EPI 0: packed QKV store to C0/C1/C2 fp32 (each stride 768)
// EPI 1: gelu(acc + bias) -> split bf16 Oh/Ol
// EPI 2: C0 += acc + bias (fp32 residual)
#define GSMEM 197632
#define STAGE_BYTES 98304

template <int EPI>
__global__ void __launch_bounds__(256) mma_gemm(
    const bf16* __restrict__ Ah, const bf16* __restrict__ Al,
    const bf16* __restrict__ Bh, const bf16* __restrict__ Bl,
    const float* __restrict__ bias,
    float* __restrict__ C0, float* __restrict__ C1, float* __restrict__ C2,
    bf16* __restrict__ Oh, bf16* __restrict__ Ol,
    int Kd, int Nc)
{
#if HAS_TCGEN05
    extern __shared__ char sm[];
    const uint32_t smem_base = smem_u32(sm);
    const int tid = threadIdx.x;
    const int bm = blockIdx.y * 128;
    const int bn = blockIdx.x * 256;

    if (tid == 0) { mbar_init(smem_base + 8, 1); mbar_init(smem_base + 16, 1); }
    if (tid < 32) { tm_alloc(smem_base, 256); tm_relinq(); }
    __syncthreads();
    uint32_t tmem;
    asm volatile("ld.shared.b32 %0, [%1];" : "=r"(tmem) : "r"(smem_base));

    const uint32_t IDESC = (1u << 4) | (1u << 7) | (1u << 10) |
                           ((256u / 8) << 17) | ((128u / 16) << 24);
    const bf16* pAh0 = Ah + (size_t)bm * Kd;
    const bf16* pAl0 = Al + (size_t)bm * Kd;
    const bf16* pBh0 = Bh + (size_t)bn * Kd;
    const bf16* pBl0 = Bl + (size_t)bn * Kd;

    const int NC = Kd >> 6;
    uint32_t ph0 = 0, ph1 = 0;

    for (int c = 0; c < NC; c++) {
        const int s = c & 1;
        if (c >= 2) {
            if (s == 0) { mbar_wait(smem_base + 8, ph0); ph0 ^= 1; }
            else        { mbar_wait(smem_base + 16, ph1); ph1 ^= 1; }
        }
        char* stc = sm + 1024 + s * STAGE_BYTES;
        const int c0 = c << 6;
#pragma unroll
        for (int it = 0; it < 4; it++) {
            int id = tid + it * 256;
            int row = id >> 3, seg = id & 7;
            uint32_t byt = (row << 7) | (seg << 4);
            uint32_t sw = byt ^ ((byt >> 3) & 0x70);
            size_t go = (size_t)row * Kd + c0 + seg * 8;
            *(uint4*)(stc + sw)         = *(const uint4*)(pAh0 + go);
            *(uint4*)(stc + 16384 + sw) = *(const uint4*)(pAl0 + go);
        }
#pragma unroll
        for (int it = 0; it < 8; it++) {
            int id = tid + it * 256;
            int row = id >> 3, seg = id & 7;
            uint32_t byt = (row << 7) | (seg << 4);
            uint32_t sw = byt ^ ((byt >> 3) & 0x70);
            size_t go = (size_t)row * Kd + c0 + seg * 8;
            *(uint4*)(stc + 32768 + sw) = *(const uint4*)(pBh0 + go);
            *(uint4*)(stc + 65536 + sw) = *(const uint4*)(pBl0 + go);
        }
        __syncthreads();
        if (tid < 32 && elect_one()) {
            asm volatile("fence.proxy.async.shared::cta;" ::: "memory");
            uint32_t su = smem_base + 1024 + s * STAGE_BYTES;
            uint64_t dAh = mkdesc(su);
            uint64_t dAl = mkdesc(su + 16384);
            uint64_t dBh = mkdesc(su + 32768);
            uint64_t dBl = mkdesc(su + 65536);
#pragma unroll
            for (int ks = 0; ks < 4; ks++)
                mma_f16_ss(tmem, dAh + ks * 2, dBh + ks * 2, IDESC, (c > 0) | (ks > 0));
#pragma unroll
            for (int ks = 0; ks < 4; ks++)
                mma_f16_ss(tmem, dAl + ks * 2, dBh + ks * 2, IDESC, 1);
#pragma unroll
            for (int ks = 0; ks < 4; ks++)
                mma_f16_ss(tmem, dAh + ks * 2, dBl + ks * 2, IDESC, 1);
            tm_commit(smem_base + 8 + 8 * s);
        }
    }
    mbar_wait(smem_base + 8, ph0);
    mbar_wait(smem_base + 16, ph1);
    asm volatile("tcgen05.fence::after_thread_sync;" ::: "memory");

    // stage D through smem (transposed-coalesced writeout)
    const int w = tid >> 5, lane = tid & 31;
    const int cb = (w >> 2) * 128;
    const int r = (w & 3) * 32 + lane;
    float* Cs = (float*)(sm + 1024);
#pragma unroll
    for (int cc = 0; cc < 4; cc++) {
        uint32_t regs[32];
        LDTM_X32(regs, tmem + cb + cc * 32);
        asm volatile("tcgen05.wait::ld.sync.aligned;" ::: "memory");
#pragma unroll
        for (int j = 0; j < 32; j++)
            Cs[r * 257 + cb + cc * 32 + j] = __uint_as_float(regs[j]);
    }
    asm volatile("tcgen05.fence::before_thread_sync;" ::: "memory");
    __syncthreads();

    if (EPI == 0) {
        float* dst; int nb = bn;
        if (nb < 768) dst = C0;
        else if (nb < 1536) { dst = C1; nb -= 768; }
        else { dst = C2; nb -= 1536; }
#pragma unroll 4
        for (int it = 0; it < 128; it++)
            dst[(size_t)(bm + it) * 768 + nb + tid] = Cs[it * 257 + tid];
    } else if (EPI == 1) {
        float bb = bias[bn + tid];
#pragma unroll 4
        for (int it = 0; it < 128; it++) {
            float g = gelu_tanh(Cs[it * 257 + tid] + bb);
            bf16 h, l; split_bf16(g, h, l);
            size_t o = (size_t)(bm + it) * Nc + bn + tid;
            Oh[o] = h; Ol[o] = l;
        }
    } else {
        float bb = bias[bn + tid];
#pragma unroll 4
        for (int it = 0; it < 128; it++) {
            size_t o = (size_t)(bm + it) * Nc + bn + tid;
            C0[o] += Cs[it * 257 + tid] + bb;
        }
    }
    __syncthreads();
    if (tid == 0) { mbar_inval(smem_base + 8); mbar_inval(smem_base + 16); }
    if (tid < 32) tm_dealloc(tmem, 256);
#else
    // correct-but-slow fallback for the non-arch-specific compile pass
    const int tid = threadIdx.x;
    const int bm = blockIdx.y * 128;
    const int bn = blockIdx.x * 256;
    for (int e = tid; e < 128 * 256; e += 256) {
        int r = e >> 8, c = e & 255;
        const bf16* ah = Ah + (size_t)(bm + r) * Kd;
        const bf16* al = Al + (size_t)(bm + r) * Kd;
        const bf16* wh = Bh + (size_t)(bn + c) * Kd;
        const bf16* wl = Bl + (size_t)(bn + c) * Kd;
        float s = 0.f;
        for (int k = 0; k < Kd; k++) {
            float a = __bfloat162float(ah[k]) + __bfloat162float(al[k]);
            float b = __bfloat162float(wh[k]) + __bfloat162float(wl[k]);
            s += a * b;
        }
        if (EPI == 0) {
            float* dst; int nb = bn + c;
            if (nb < 768) dst = C0;
            else if (nb < 1536) { dst = C1; nb -= 768; }
            else { dst = C2; nb -= 1536; }
            dst[(size_t)(bm + r) * 768 + nb] = s;
        } else if (EPI == 1) {
            float g = gelu_tanh(s + bias[bn + c]);
            bf16 h, l; split_bf16(g, h, l);
            size_t o = (size_t)(bm + r) * Nc + bn + c;
            Oh[o] = h; Ol[o] = l;
        } else {
            size_t o = (size_t)(bm + r) * Nc + bn + c;
            C0[o] += s + bias[bn + c];
        }
    }
#endif
}

// ---------------- Time attention (T=32) ----------------
__global__ void __launch_bounds__(32) attn_time_kernel(
    const float* __restrict__ q, const float* __restrict__ k,
    const float* __restrict__ v, bf16* __restrict__ oh, bf16* __restrict__ ol)
{
    __shared__ float Ks[32][64];
    __shared__ float Vs[32][64];
    __shared__ float Qs[64][33];
    int bl = blockIdx.x;
    int h = blockIdx.y;
    int b = bl / LL, l = bl % LL;
    int tid = threadIdx.x;
    size_t colbase = (size_t)h * HD;

    for (int e = tid; e < 32 * 64; e += 32) {
        int j = e >> 6, d = e & 63;
        size_t off = ((size_t)(b * TT + j) * LL + l) * DD + colbase + d;
        Ks[j][d] = k[off];
        Vs[j][d] = v[off];
        Qs[d][j] = q[off];
    }
    __syncwarp();

    float qr[64];
#pragma unroll
    for (int d = 0; d < 64; d++) qr[d] = Qs[d][tid];

    float sc_[32];
#pragma unroll 4
    for (int j = 0; j < 32; j++) {
        float s = 0.f;
        const float4* kr = (const float4*)Ks[j];
#pragma unroll
        for (int d4 = 0; d4 < 16; d4++) {
            float4 kk = kr[d4];
            s += qr[d4 * 4 + 0] * kk.x + qr[d4 * 4 + 1] * kk.y
               + qr[d4 * 4 + 2] * kk.z + qr[d4 * 4 + 3] * kk.w;
        }
        sc_[j] = s * 0.125f;
    }
    float m = sc_[0];
#pragma unroll
    for (int j = 1; j < 32; j++) m = fmaxf(m, sc_[j]);
    float lsum = 0.f;
#pragma unroll
    for (int j = 0; j < 32; j++) { sc_[j] = __expf(sc_[j] - m); lsum += sc_[j]; }
    float inv = 1.0f / lsum;

#pragma unroll
    for (int d4 = 0; d4 < 16; d4++) {
        float ax = 0.f, ay = 0.f, az = 0.f, aw = 0.f;
#pragma unroll
        for (int j = 0; j < 32; j++) {
            float4 vv = ((const float4*)Vs[j])[d4];
            float w = sc_[j];
            ax += w * vv.x; ay += w * vv.y; az += w * vv.z; aw += w * vv.w;
        }
        Qs[d4 * 4 + 0][tid] = ax * inv;
        Qs[d4 * 4 + 1][tid] = ay * inv;
        Qs[d4 * 4 + 2][tid] = az * inv;
        Qs[d4 * 4 + 3][tid] = aw * inv;
    }
    __syncwarp();
    for (int e = tid; e < 32 * 64; e += 32) {
        int j = e >> 6, d = e & 63;
        size_t off = ((size_t)(b * TT + j) * LL + l) * DD + colbase + d;
        bf16 h2, l2; split_bf16(Qs[d][j], h2, l2);
        oh[off] = h2; ol[off] = l2;
    }
}

// ---------------- Space attention (L=256) ----------------
#define SPACE_SMEM ((64 * 257 + 64 * 64 + 64 * 64) * 4)
__global__ void __launch_bounds__(256) attn_space_kernel(
    const float* __restrict__ q, const float* __restrict__ k,
    const float* __restrict__ v, bf16* __restrict__ oh, bf16* __restrict__ ol)
{
    extern __shared__ float smf[];
    float(*Qs)[257] = (float(*)[257])smf;
    float* Ks = smf + 64 * 257;
    float* Vs = Ks + 64 * 64;
    int gid = blockIdx.x;
    int h = gid % HH;
    int bt = gid / HH;
    int tid = threadIdx.x;
    size_t rowbase = (size_t)bt * LL;
    size_t colbase = (size_t)h * HD;

    for (int e = tid; e < 256 * 64; e += 256) {
        int j = e >> 6, d = e & 63;
        Qs[d][j] = q[(rowbase + j) * DD + colbase + d];
    }
    __syncthreads();

    float qr[64];
#pragma unroll
    for (int d = 0; d < 64; d++) qr[d] = Qs[d][tid];

    float m = -1e30f, lsum = 0.f;
    float acc[64];
#pragma unroll
    for (int d = 0; d < 64; d++) acc[d] = 0.f;

    for (int c0 = 0; c0 < LL; c0 += 64) {
        __syncthreads();
        for (int e = tid; e < 64 * 64; e += 256) {
            int j = e >> 6, d = e & 63;
            size_t off = (rowbase + c0 + j) * DD + colbase + d;
            Ks[e] = k[off];
            Vs[e] = v[off];
        }
        __syncthreads();
        for (int j = 0; j < 64; j++) {
            float s = 0.f;
            const float4* kr = (const float4*)(Ks + j * 64);
#pragma unroll
            for (int d4 = 0; d4 < 16; d4++) {
                float4 kk = kr[d4];
                s += qr[d4 * 4 + 0] * kk.x + qr[d4 * 4 + 1] * kk.y
                   + qr[d4 * 4 + 2] * kk.z + qr[d4 * 4 + 3] * kk.w;
            }
            s *= 0.125f;
            float mn = fmaxf(m, s);
            float corr = __expf(m - mn);
            float p = __expf(s - mn);
            lsum = lsum * corr + p;
            m = mn;
            const float4* vr = (const float4*)(Vs + j * 64);
#pragma unroll
            for (int d4 = 0; d4 < 16; d4++) {
                float4 vv = vr[d4];
                acc[d4 * 4 + 0] = acc[d4 * 4 + 0] * corr + p * vv.x;
                acc[d4 * 4 + 1] = acc[d4 * 4 + 1] * corr + p * vv.y;
                acc[d4 * 4 + 2] = acc[d4 * 4 + 2] * corr + p * vv.z;
                acc[d4 * 4 + 3] = acc[d4 * 4 + 3] * corr + p * vv.w;
            }
        }
    }
    float inv = 1.0f / lsum;
    __syncthreads();
#pragma unroll
    for (int d = 0; d < 64; d++) Qs[d][tid] = acc[d] * inv;
    __syncthreads();
    for (int e = tid; e < 256 * 64; e += 256) {
        int j = e >> 6, d = e & 63;
        size_t off = (rowbase + j) * DD + colbase + d;
        bf16 h2, l2; split_bf16(Qs[d][j], h2, l2);
        oh[off] = h2; ol[off] = l2;
    }
}

// ---------------- host launch ----------------
extern "C" void kernel_launch(void* const* d_in, const int* in_sizes, int n_in,
                              void* d_out, int out_size)
{
    const float* inp   = (const float*)d_in[0];
    const float* Wq_t  = (const float*)d_in[1];
    const float* Wk_t  = (const float*)d_in[2];
    const float* Wv_t  = (const float*)d_in[3];
    const float* Wo_t  = (const float*)d_in[4];
    const float* bo_t  = (const float*)d_in[5];
    const float* Wq_s  = (const float*)d_in[6];
    const float* Wk_s  = (const float*)d_in[7];
    const float* Wv_s  = (const float*)d_in[8];
    const float* Wo_s  = (const float*)d_in[9];
    const float* bo_s  = (const float*)d_in[10];
    const float* ln_ts = (const float*)d_in[11];
    const float* ln_tb = (const float*)d_in[12];
    const float* ln_ss = (const float*)d_in[13];
    const float* ln_sb = (const float*)d_in[14];
    const float* ln2s  = (const float*)d_in[15];
    const float* ln2b  = (const float*)d_in[16];
    const float* W1    = (const float*)d_in[17];
    const float* b1    = (const float*)d_in[18];
    const float* W2    = (const float*)d_in[19];
    const float* b2    = (const float*)d_in[20];
    float* out = (float*)d_out;

    cudaFuncSetAttribute(attn_space_kernel,
                         cudaFuncAttributeMaxDynamicSharedMemorySize, SPACE_SMEM);
    cudaFuncSetAttribute(mma_gemm<0>, cudaFuncAttributeMaxDynamicSharedMemorySize, GSMEM);
    cudaFuncSetAttribute(mma_gemm<1>, cudaFuncAttributeMaxDynamicSharedMemorySize, GSMEM);
    cudaFuncSetAttribute(mma_gemm<2>, cudaFuncAttributeMaxDynamicSharedMemorySize, GSMEM);

    float *gq, *gk, *gv;
    bf16 *gxh, *gxl, *gah, *gal, *gfh, *gfl, *wth, *wtl;
    cudaGetSymbolAddress((void**)&gq, g_q);
    cudaGetSymbolAddress((void**)&gk, g_k);
    cudaGetSymbolAddress((void**)&gv, g_v);
    cudaGetSymbolAddress((void**)&gxh, g_xh);
    cudaGetSymbolAddress((void**)&gxl, g_xl);
    cudaGetSymbolAddress((void**)&gah, g_ah);
    cudaGetSymbolAddress((void**)&gal, g_al);
    cudaGetSymbolAddress((void**)&gfh, g_ffh);
    cudaGetSymbolAddress((void**)&gfl, g_ffl);
    cudaGetSymbolAddress((void**)&wth, g_wth);
    cudaGetSymbolAddress((void**)&wtl, g_wtl);

    cudaMemcpyAsync(out, inp, (size_t)NTOK * DD * sizeof(float),
                    cudaMemcpyDeviceToDevice);

    // convert + transpose + split all weights
    dim3 cb(32, 8);
    for (int lyr = 0; lyr < NLAYER; lyr++) {
        size_t wo  = (size_t)lyr * DD * DD;
        size_t w1o = (size_t)lyr * DD * FFW_;
        size_t base = (size_t)lyr * WT_LAYER;
        dim3 gdd(DD / 32, DD / 32);
        convT<<<gdd, cb>>>(Wq_t + wo, wth + base + WT_QKV_T,           wtl + base + WT_QKV_T,           DD, DD);
        convT<<<gdd, cb>>>(Wk_t + wo, wth + base + WT_QKV_T + 589824,  wtl + base + WT_QKV_T + 589824,  DD, DD);
        convT<<<gdd, cb>>>(Wv_t + wo, wth + base + WT_QKV_T + 1179648, wtl + base + WT_QKV_T + 1179648, DD, DD);
        convT<<<gdd, cb>>>(Wq_s + wo, wth + base + WT_QKV_S,           wtl + base + WT_QKV_S,           DD, DD);
        convT<<<gdd, cb>>>(Wk_s + wo, wth + base + WT_QKV_S + 589824,  wtl + base + WT_QKV_S + 589824,  DD, DD);
        convT<<<gdd, cb>>>(Wv_s + wo, wth + base + WT_QKV_S + 1179648, wtl + base + WT_QKV_S + 1179648, DD, DD);
        convT<<<gdd, cb>>>(Wo_t + wo, wth + base + WT_WO_T, wtl + base + WT_WO_T, DD, DD);
        convT<<<gdd, cb>>>(Wo_s + wo, wth + base + WT_WO_S, wtl + base + WT_WO_S, DD, DD);
        convT<<<dim3(FFW_ / 32, DD / 32), cb>>>(W1 + w1o, wth + base + WT_W1, wtl + base + WT_W1, DD, FFW_);
        convT<<<dim3(DD / 32, FFW_ / 32), cb>>>(W2 + w1o, wth + base + WT_W2, wtl + base + WT_W2, FFW_, DD);
    }

    dim3 gQKV(9, 128), gO(3, 128), gF1(12, 128), gF2(3, 128);

    for (int lyr = 0; lyr < NLAYER; lyr++) {
        size_t vo = (size_t)lyr * DD;
        size_t fo = (size_t)lyr * FFW_;
        size_t base = (size_t)lyr * WT_LAYER;

        // ---- time attention block ----
        ln_kernel<<<NTOK, 256>>>(out, ln_ts + vo, ln_tb + vo, gxh, gxl);
        mma_gemm<0><<<gQKV, 256, GSMEM>>>(gxh, gxl,
            wth + base + WT_QKV_T, wtl + base + WT_QKV_T,
            nullptr, gq, gk, gv, nullptr, nullptr, DD, 2304);
        attn_time_kernel<<<dim3(NB * LL, HH), 32>>>(gq, gk, gv, gah, gal);
        mma_gemm<2><<<gO, 256, GSMEM>>>(gah, gal,
            wth + base + WT_WO_T, wtl + base + WT_WO_T,
            bo_t + vo, out, nullptr, nullptr, nullptr, nullptr, DD, DD);

        // ---- space attention block ----
        ln_kernel<<<NTOK, 256>>>(out, ln_ss + vo, ln_sb + vo, gxh, gxl);
        mma_gemm<0><<<gQKV, 256, GSMEM>>>(gxh, gxl,
            wth + base + WT_QKV_S, wtl + base + WT_QKV_S,
            nullptr, gq, gk, gv, nullptr, nullptr, DD, 2304);
        attn_space_kernel<<<NB * TT * HH, 256, SPACE_SMEM>>>(gq, gk, gv, gah, gal);
        mma_gemm<2><<<gO, 256, GSMEM>>>(gah, gal,
            wth + base + WT_WO_S, wtl + base + WT_WO_S,
            bo_s + vo, out, nullptr, nullptr, nullptr, nullptr, DD, DD);

        // ---- FFN block ----
        ln_kernel<<<NTOK, 256>>>(out, ln2s + vo, ln2b + vo, gxh, gxl);
        mma_gemm<1><<<gF1, 256, GSMEM>>>(gxh, gxl,
            wth + base + WT_W1, wtl + base + WT_W1,
            b1 + fo, nullptr, nullptr, nullptr, gfh, gfl, DD, FFW_);
        mma_gemm<2><<<gF2, 256, GSMEM>>>(gfh, gfl,
            wth + base + WT_W2, wtl + base + WT_W2,
            b2 + vo, out, nullptr, nullptr, nullptr, nullptr, FFW_, DD);
    }
}

// round 8
// speedup vs baseline: 3.3998x; 1.4540x over previous
#include <cuda_runtime.h>
#include <cuda_bf16.h>
#include <cstdint>
#include <math.h>

#define NB 2
#define TT 32
#define LL 256
#define DD 768
#define HH 12
#define HD 64
#define FFW_ 3072
#define NLAYER 4
#define NTOK (NB*TT*LL)   // 16384

typedef __nv_bfloat16 bf16;

#if defined(__CUDA_ARCH_FEAT_SM103_ALL) || defined(__CUDA_ARCH_FEAT_SM100_ALL) || defined(__CUDA_ARCH_FEAT_SM101_ALL)
#define HAS_TCGEN05 1
#else
#define HAS_TCGEN05 0
#endif

// ---------------- scratch (device globals, no allocation) ----------------
__device__ float g_q[(size_t)NTOK*DD];
__device__ float g_k[(size_t)NTOK*DD];
__device__ float g_v[(size_t)NTOK*DD];
__device__ bf16  g_xh[(size_t)NTOK*DD];
__device__ bf16  g_xl[(size_t)NTOK*DD];
__device__ bf16  g_ah[(size_t)NTOK*DD];
__device__ bf16  g_al[(size_t)NTOK*DD];
__device__ bf16  g_ffh[(size_t)NTOK*FFW_];
__device__ bf16  g_ffl[(size_t)NTOK*FFW_];

// transposed split weights [N,K] per layer
#define WT_QKV_T 0
#define WT_QKV_S 1769472
#define WT_WO_T  3538944
#define WT_WO_S  4128768
#define WT_W1    4718592
#define WT_W2    7077888
#define WT_LAYER 9437184
__device__ bf16 g_wth[(size_t)WT_LAYER*NLAYER];
__device__ bf16 g_wtl[(size_t)WT_LAYER*NLAYER];

// ---------------- helpers ----------------
__device__ __forceinline__ uint32_t smem_u32(const void* p) {
    uint32_t a;
    asm("{ .reg .u64 t; cvta.to.shared.u64 t, %1; cvt.u32.u64 %0, t; }" : "=r"(a) : "l"(p));
    return a;
}
__device__ __forceinline__ void cp16(uint32_t s, const void* g) {
    asm volatile("cp.async.cg.shared.global [%0], [%1], 16;" :: "r"(s), "l"(g));
}
__device__ __forceinline__ void cp_commit() {
    asm volatile("cp.async.commit_group;" ::: "memory");
}
__device__ __forceinline__ void cp_wait1() {
    asm volatile("cp.async.wait_group 1;" ::: "memory");
}
__device__ __forceinline__ void cp_wait0() {
    asm volatile("cp.async.wait_group 0;" ::: "memory");
}
__device__ __forceinline__ void split_bf16(float v, bf16& h, bf16& l) {
    h = __float2bfloat16(v);
    l = __float2bfloat16(v - __bfloat162float(h));
}
__device__ __forceinline__ float gelu_tanh(float x) {
    float x3 = x * x * x;
    return 0.5f * x * (1.0f + tanhf(0.7978845608028654f * (x + 0.044715f * x3)));
}

#if HAS_TCGEN05
__device__ __forceinline__ uint32_t elect_one() {
    uint32_t p;
    asm volatile("{\n\t.reg .pred p;\n\telect.sync _|p, 0xFFFFFFFF;\n\tselp.b32 %0, 1, 0, p;\n\t}" : "=r"(p));
    return p;
}
__device__ __forceinline__ void mbar_init(uint32_t a, uint32_t c) {
    asm volatile("mbarrier.init.shared.b64 [%0], %1;" :: "r"(a), "r"(c) : "memory");
}
__device__ __forceinline__ void mbar_inval(uint32_t a) {
    asm volatile("mbarrier.inval.shared.b64 [%0];" :: "r"(a) : "memory");
}
__device__ __forceinline__ void mbar_wait(uint32_t a, uint32_t ph) {
    uint32_t done = 0;
    while (!done) {
        asm volatile(
            "{\n\t.reg .pred p;\n\t"
            "mbarrier.try_wait.parity.acquire.cta.shared::cta.b64 p, [%1], %2, 0x989680;\n\t"
            "selp.b32 %0, 1, 0, p;\n\t}"
            : "=r"(done) : "r"(a), "r"(ph) : "memory");
    }
}
__device__ __forceinline__ void tm_alloc(uint32_t dst, uint32_t n) {
    asm volatile("tcgen05.alloc.cta_group::1.sync.aligned.shared::cta.b32 [%0], %1;"
                 :: "r"(dst), "r"(n) : "memory");
}
__device__ __forceinline__ void tm_relinq() {
    asm volatile("tcgen05.relinquish_alloc_permit.cta_group::1.sync.aligned;");
}
__device__ __forceinline__ void tm_dealloc(uint32_t t, uint32_t n) {
    asm volatile("tcgen05.dealloc.cta_group::1.sync.aligned.b32 %0, %1;" :: "r"(t), "r"(n));
}
__device__ __forceinline__ void tm_commit(uint32_t mbar) {
    asm volatile("tcgen05.commit.cta_group::1.mbarrier::arrive::one.shared::cluster.b64 [%0];"
                 :: "r"(mbar) : "memory");
}
__device__ __forceinline__ void mma_f16_ss(uint32_t d, uint64_t a, uint64_t b,
                                           uint32_t idesc, uint32_t en) {
    asm volatile(
        "{\n\t.reg .pred p;\n\tsetp.ne.u32 p, %4, 0;\n\t"
        "tcgen05.mma.cta_group::1.kind::f16 [%0], %1, %2, %3, {%5, %5, %5, %5}, p;\n\t}"
        :: "r"(d), "l"(a), "l"(b), "r"(idesc), "r"(en), "r"(0u) : "memory");
}
__device__ __forceinline__ uint64_t mkdesc(uint32_t addr) {
    return (((uint64_t)2 << 61) | ((uint64_t)1 << 46) | ((uint64_t)64 << 32) |
            ((uint64_t)1 << 16)) | (uint64_t)((addr >> 4) & 0x3FFF);
}
#define LDTM_X32(r, a) \
    asm volatile( \
        "tcgen05.ld.sync.aligned.32x32b.x32.b32 " \
        "{%0, %1, %2, %3, %4, %5, %6, %7, " \
        " %8, %9, %10, %11, %12, %13, %14, %15, " \
        " %16, %17, %18, %19, %20, %21, %22, %23, " \
        " %24, %25, %26, %27, %28, %29, %30, %31}, [%32];" \
        : "=r"((r)[0]),  "=r"((r)[1]),  "=r"((r)[2]),  "=r"((r)[3]), \
          "=r"((r)[4]),  "=r"((r)[5]),  "=r"((r)[6]),  "=r"((r)[7]), \
          "=r"((r)[8]),  "=r"((r)[9]),  "=r"((r)[10]), "=r"((r)[11]), \
          "=r"((r)[12]), "=r"((r)[13]), "=r"((r)[14]), "=r"((r)[15]), \
          "=r"((r)[16]), "=r"((r)[17]), "=r"((r)[18]), "=r"((r)[19]), \
          "=r"((r)[20]), "=r"((r)[21]), "=r"((r)[22]), "=r"((r)[23]), \
          "=r"((r)[24]), "=r"((r)[25]), "=r"((r)[26]), "=r"((r)[27]), \
          "=r"((r)[28]), "=r"((r)[29]), "=r"((r)[30]), "=r"((r)[31]) \
        : "r"(a))
#endif

// ---------------- weight convert + transpose + bf16 split ----------------
__global__ void convT(const float* __restrict__ W, bf16* __restrict__ th,
                      bf16* __restrict__ tl, int K, int N)
{
    __shared__ float t[32][33];
    int n0 = blockIdx.x * 32, k0 = blockIdx.y * 32;
    int tx = threadIdx.x, ty = threadIdx.y; // (32,8)
#pragma unroll
    for (int r = 0; r < 4; r++) {
        int k = k0 + ty + r * 8;
        t[ty + r * 8][tx] = W[(size_t)k * N + n0 + tx];
    }
    __syncthreads();
#pragma unroll
    for (int r = 0; r < 4; r++) {
        int n = n0 + ty + r * 8;
        float v = t[tx][ty + r * 8];
        bf16 h, l; split_bf16(v, h, l);
        th[(size_t)n * K + k0 + tx] = h;
        tl[(size_t)n * K + k0 + tx] = l;
    }
}

// ---------------- LayerNorm -> split bf16 ----------------
__global__ void ln_kernel(const float* __restrict__ h, const float* __restrict__ sc,
                          const float* __restrict__ bi,
                          bf16* __restrict__ xh, bf16* __restrict__ xl)
{
    int row = blockIdx.x;
    const float* hr = h + (size_t)row * DD;
    int tid = threadIdx.x;
    float v0 = hr[tid], v1 = hr[tid + 256], v2 = hr[tid + 512];
    __shared__ float red[256];
    red[tid] = v0 + v1 + v2;
    __syncthreads();
    for (int o = 128; o > 0; o >>= 1) {
        if (tid < o) red[tid] += red[tid + o];
        __syncthreads();
    }
    float mean = red[0] * (1.0f / DD);
    __syncthreads();
    float d0 = v0 - mean, d1 = v1 - mean, d2 = v2 - mean;
    red[tid] = d0 * d0 + d1 * d1 + d2 * d2;
    __syncthreads();
    for (int o = 128; o > 0; o >>= 1) {
        if (tid < o) red[tid] += red[tid + o];
        __syncthreads();
    }
    float rstd = rsqrtf(red[0] * (1.0f / DD) + 1e-5f);
    size_t base = (size_t)row * DD;
    float y0 = d0 * rstd * sc[tid]       + bi[tid];
    float y1 = d1 * rstd * sc[tid + 256] + bi[tid + 256];
    float y2 = d2 * rstd * sc[tid + 512] + bi[tid + 512];
    bf16 hh, ll;
    split_bf16(y0, hh, ll); xh[base + tid] = hh;       xl[base + tid] = ll;
    split_bf16(y1, hh, ll); xh[base + tid + 256] = hh; xl[base + tid + 256] = ll;
    split_bf16(y2, hh, ll); xh[base + tid + 512] = hh; xl[base + tid + 512] = ll;
}

// ---------------- tcgen05 GEMM: C[M,Nc] = A[M,Kd] @ B[Nc,Kd]^T ----------------
// bf16x3 split: Ah*Bh + Al*Bh + Ah*Bl, fp32 accum in TMEM.
// Tile 128x256, double-buffered 96KB stages, cp.async producer.
// EPI 0: packed QKV store to C0/C1/C2 fp32 (each stride 768)
// EPI 1: gelu(acc + bias) -> split bf16 Oh/Ol
// EPI 2: C0 += acc + bias (fp32 residual)
#define GSMEM 197632
#define STAGE_BYTES 98304

template <int EPI>
__global__ void __launch_bounds__(256) mma_gemm(
    const bf16* __restrict__ Ah, const bf16* __restrict__ Al,
    const bf16* __restrict__ Bh, const bf16* __restrict__ Bl,
    const float* __restrict__ bias,
    float* __restrict__ C0, float* __restrict__ C1, float* __restrict__ C2,
    bf16* __restrict__ Oh, bf16* __restrict__ Ol,
    int Kd, int Nc)
{
#if HAS_TCGEN05
    extern __shared__ char sm[];
    const uint32_t smem_base = smem_u32(sm);
    const int tid = threadIdx.x;
    const int bm = blockIdx.y * 128;
    const int bn = blockIdx.x * 256;

    if (tid == 0) { mbar_init(smem_base + 8, 1); mbar_init(smem_base + 16, 1); }
    if (tid < 32) { tm_alloc(smem_base, 256); tm_relinq(); }
    __syncthreads();
    uint32_t tmem;
    asm volatile("ld.shared.b32 %0, [%1];" : "=r"(tmem) : "r"(smem_base));

    const uint32_t IDESC = (1u << 4) | (1u << 7) | (1u << 10) |
                           ((256u / 8) << 17) | ((128u / 16) << 24);
    const bf16* pAh0 = Ah + (size_t)bm * Kd;
    const bf16* pAl0 = Al + (size_t)bm * Kd;
    const bf16* pBh0 = Bh + (size_t)bn * Kd;
    const bf16* pBl0 = Bl + (size_t)bn * Kd;

    const int NC = Kd >> 6;
    uint32_t ph0 = 0, ph1 = 0;

    // per-thread producer addressing (same for every chunk)
    const int arow = tid >> 3;            // A: 4 iters cover rows 0..127 step 32
    const int seg  = tid & 7;
    const uint32_t swA = [&] {
        uint32_t byt = ((uint32_t)arow << 7) | ((uint32_t)seg << 4);
        return byt ^ ((byt >> 3) & 0x70);
    }();

    auto load_chunk = [&](int c, int s) {
        const uint32_t su = smem_base + 1024 + (uint32_t)s * STAGE_BYTES;
        const int c0 = c << 6;
#pragma unroll
        for (int it = 0; it < 4; it++) {
            int row = arow + it * 32;
            uint32_t byt = ((uint32_t)row << 7) | ((uint32_t)seg << 4);
            uint32_t sw = byt ^ ((byt >> 3) & 0x70);
            size_t go = (size_t)row * Kd + c0 + seg * 8;
            cp16(su + sw,         pAh0 + go);
            cp16(su + 16384 + sw, pAl0 + go);
        }
#pragma unroll
        for (int it = 0; it < 8; it++) {
            int row = arow + it * 32;
            uint32_t byt = ((uint32_t)row << 7) | ((uint32_t)seg << 4);
            uint32_t sw = byt ^ ((byt >> 3) & 0x70);
            size_t go = (size_t)row * Kd + c0 + seg * 8;
            cp16(su + 32768 + sw, pBh0 + go);
            cp16(su + 65536 + sw, pBl0 + go);
        }
        cp_commit();
    };
    (void)swA;

    // prologue: stage 0 <- chunk0, stage 1 <- chunk1
    load_chunk(0, 0);
    load_chunk(1, 1);

    for (int c = 0; c < NC; c++) {
        const int s = c & 1;
        if (c + 1 < NC) cp_wait1(); else cp_wait0();
        __syncthreads();
        if (tid < 32 && elect_one()) {
            asm volatile("fence.proxy.async.shared::cta;" ::: "memory");
            uint32_t su = smem_base + 1024 + (uint32_t)s * STAGE_BYTES;
            uint64_t dAh = mkdesc(su);
            uint64_t dAl = mkdesc(su + 16384);
            uint64_t dBh = mkdesc(su + 32768);
            uint64_t dBl = mkdesc(su + 65536);
#pragma unroll
            for (int ks = 0; ks < 4; ks++)
                mma_f16_ss(tmem, dAh + ks * 2, dBh + ks * 2, IDESC, (c > 0) | (ks > 0));
#pragma unroll
            for (int ks = 0; ks < 4; ks++)
                mma_f16_ss(tmem, dAl + ks * 2, dBh + ks * 2, IDESC, 1);
#pragma unroll
            for (int ks = 0; ks < 4; ks++)
                mma_f16_ss(tmem, dAh + ks * 2, dBl + ks * 2, IDESC, 1);
            tm_commit(smem_base + 8 + 8 * s);
        }
        if (c + 2 < NC) {
            // stage s is reused by chunk c+2: wait MMA(c) to finish reading it
            if (s == 0) { mbar_wait(smem_base + 8, ph0); ph0 ^= 1; }
            else        { mbar_wait(smem_base + 16, ph1); ph1 ^= 1; }
            load_chunk(c + 2, s);
        }
    }
    mbar_wait(smem_base + 8, ph0);
    mbar_wait(smem_base + 16, ph1);
    asm volatile("tcgen05.fence::after_thread_sync;" ::: "memory");

    // stage D through smem (transposed-coalesced writeout)
    const int w = tid >> 5, lane = tid & 31;
    const int cb = (w >> 2) * 128;
    const int r = (w & 3) * 32 + lane;
    float* Cs = (float*)(sm + 1024);
#pragma unroll
    for (int cc = 0; cc < 4; cc++) {
        uint32_t regs[32];
        LDTM_X32(regs, tmem + cb + cc * 32);
        asm volatile("tcgen05.wait::ld.sync.aligned;" ::: "memory");
#pragma unroll
        for (int j = 0; j < 32; j++)
            Cs[r * 257 + cb + cc * 32 + j] = __uint_as_float(regs[j]);
    }
    asm volatile("tcgen05.fence::before_thread_sync;" ::: "memory");
    __syncthreads();

    if (EPI == 0) {
        float* dst; int nb = bn;
        if (nb < 768) dst = C0;
        else if (nb < 1536) { dst = C1; nb -= 768; }
        else { dst = C2; nb -= 1536; }
#pragma unroll 4
        for (int it = 0; it < 128; it++)
            dst[(size_t)(bm + it) * 768 + nb + tid] = Cs[it * 257 + tid];
    } else if (EPI == 1) {
        float bb = bias[bn + tid];
#pragma unroll 4
        for (int it = 0; it < 128; it++) {
            float g = gelu_tanh(Cs[it * 257 + tid] + bb);
            bf16 h, l; split_bf16(g, h, l);
            size_t o = (size_t)(bm + it) * Nc + bn + tid;
            Oh[o] = h; Ol[o] = l;
        }
    } else {
        float bb = bias[bn + tid];
#pragma unroll 4
        for (int it = 0; it < 128; it++) {
            size_t o = (size_t)(bm + it) * Nc + bn + tid;
            C0[o] += Cs[it * 257 + tid] + bb;
        }
    }
    __syncthreads();
    if (tid == 0) { mbar_inval(smem_base + 8); mbar_inval(smem_base + 16); }
    if (tid < 32) tm_dealloc(tmem, 256);
#else
    // correct-but-slow fallback for the non-arch-specific compile pass
    const int tid = threadIdx.x;
    const int bm = blockIdx.y * 128;
    const int bn = blockIdx.x * 256;
    for (int e = tid; e < 128 * 256; e += 256) {
        int r = e >> 8, c = e & 255;
        const bf16* ah = Ah + (size_t)(bm + r) * Kd;
        const bf16* al = Al + (size_t)(bm + r) * Kd;
        const bf16* wh = Bh + (size_t)(bn + c) * Kd;
        const bf16* wl = Bl + (size_t)(bn + c) * Kd;
        float s = 0.f;
        for (int k = 0; k < Kd; k++) {
            float a = __bfloat162float(ah[k]) + __bfloat162float(al[k]);
            float b = __bfloat162float(wh[k]) + __bfloat162float(wl[k]);
            s += a * b;
        }
        if (EPI == 0) {
            float* dst; int nb = bn + c;
            if (nb < 768) dst = C0;
            else if (nb < 1536) { dst = C1; nb -= 768; }
            else { dst = C2; nb -= 1536; }
            dst[(size_t)(bm + r) * 768 + nb] = s;
        } else if (EPI == 1) {
            float g = gelu_tanh(s + bias[bn + c]);
            bf16 h, l; split_bf16(g, h, l);
            size_t o = (size_t)(bm + r) * Nc + bn + c;
            Oh[o] = h; Ol[o] = l;
        } else {
            size_t o = (size_t)(bm + r) * Nc + bn + c;
            C0[o] += s + bias[bn + c];
        }
    }
#endif
}

// ---------------- Time attention (T=32) ----------------
__global__ void __launch_bounds__(32) attn_time_kernel(
    const float* __restrict__ q, const float* __restrict__ k,
    const float* __restrict__ v, bf16* __restrict__ oh, bf16* __restrict__ ol)
{
    __shared__ float Ks[32][64];
    __shared__ float Vs[32][64];
    __shared__ float Qs[64][33];
    int bl = blockIdx.x;
    int h = blockIdx.y;
    int b = bl / LL, l = bl % LL;
    int tid = threadIdx.x;
    size_t colbase = (size_t)h * HD;

    for (int e = tid; e < 32 * 64; e += 32) {
        int j = e >> 6, d = e & 63;
        size_t off = ((size_t)(b * TT + j) * LL + l) * DD + colbase + d;
        Ks[j][d] = k[off];
        Vs[j][d] = v[off];
        Qs[d][j] = q[off];
    }
    __syncwarp();

    float qr[64];
#pragma unroll
    for (int d = 0; d < 64; d++) qr[d] = Qs[d][tid];

    float sc_[32];
#pragma unroll 4
    for (int j = 0; j < 32; j++) {
        float s = 0.f;
        const float4* kr = (const float4*)Ks[j];
#pragma unroll
        for (int d4 = 0; d4 < 16; d4++) {
            float4 kk = kr[d4];
            s += qr[d4 * 4 + 0] * kk.x + qr[d4 * 4 + 1] * kk.y
               + qr[d4 * 4 + 2] * kk.z + qr[d4 * 4 + 3] * kk.w;
        }
        sc_[j] = s * 0.125f;
    }
    float m = sc_[0];
#pragma unroll
    for (int j = 1; j < 32; j++) m = fmaxf(m, sc_[j]);
    float lsum = 0.f;
#pragma unroll
    for (int j = 0; j < 32; j++) { sc_[j] = __expf(sc_[j] - m); lsum += sc_[j]; }
    float inv = 1.0f / lsum;

#pragma unroll
    for (int d4 = 0; d4 < 16; d4++) {
        float ax = 0.f, ay = 0.f, az = 0.f, aw = 0.f;
#pragma unroll
        for (int j = 0; j < 32; j++) {
            float4 vv = ((const float4*)Vs[j])[d4];
            float w = sc_[j];
            ax += w * vv.x; ay += w * vv.y; az += w * vv.z; aw += w * vv.w;
        }
        Qs[d4 * 4 + 0][tid] = ax * inv;
        Qs[d4 * 4 + 1][tid] = ay * inv;
        Qs[d4 * 4 + 2][tid] = az * inv;
        Qs[d4 * 4 + 3][tid] = aw * inv;
    }
    __syncwarp();
    for (int e = tid; e < 32 * 64; e += 32) {
        int j = e >> 6, d = e & 63;
        size_t off = ((size_t)(b * TT + j) * LL + l) * DD + colbase + d;
        bf16 h2, l2; split_bf16(Qs[d][j], h2, l2);
        oh[off] = h2; ol[off] = l2;
    }
}

// ---------------- Space attention (L=256) ----------------
#define SPACE_SMEM ((64 * 257 + 64 * 64 + 64 * 64) * 4)
__global__ void __launch_bounds__(256) attn_space_kernel(
    const float* __restrict__ q, const float* __restrict__ k,
    const float* __restrict__ v, bf16* __restrict__ oh, bf16* __restrict__ ol)
{
    extern __shared__ float smf[];
    float(*Qs)[257] = (float(*)[257])smf;
    float* Ks = smf + 64 * 257;
    float* Vs = Ks + 64 * 64;
    int gid = blockIdx.x;
    int h = gid % HH;
    int bt = gid / HH;
    int tid = threadIdx.x;
    size_t rowbase = (size_t)bt * LL;
    size_t colbase = (size_t)h * HD;

    for (int e = tid; e < 256 * 64; e += 256) {
        int j = e >> 6, d = e & 63;
        Qs[d][j] = q[(rowbase + j) * DD + colbase + d];
    }
    __syncthreads();

    float qr[64];
#pragma unroll
    for (int d = 0; d < 64; d++) qr[d] = Qs[d][tid];

    float m = -1e30f, lsum = 0.f;
    float acc[64];
#pragma unroll
    for (int d = 0; d < 64; d++) acc[d] = 0.f;

    for (int c0 = 0; c0 < LL; c0 += 64) {
        __syncthreads();
        for (int e = tid; e < 64 * 64; e += 256) {
            int j = e >> 6, d = e & 63;
            size_t off = (rowbase + c0 + j) * DD + colbase + d;
            Ks[e] = k[off];
            Vs[e] = v[off];
        }
        __syncthreads();
        for (int j = 0; j < 64; j++) {
            float s = 0.f;
            const float4* kr = (const float4*)(Ks + j * 64);
#pragma unroll
            for (int d4 = 0; d4 < 16; d4++) {
                float4 kk = kr[d4];
                s += qr[d4 * 4 + 0] * kk.x + qr[d4 * 4 + 1] * kk.y
                   + qr[d4 * 4 + 2] * kk.z + qr[d4 * 4 + 3] * kk.w;
            }
            s *= 0.125f;
            float mn = fmaxf(m, s);
            float corr = __expf(m - mn);
            float p = __expf(s - mn);
            lsum = lsum * corr + p;
            m = mn;
            const float4* vr = (const float4*)(Vs + j * 64);
#pragma unroll
            for (int d4 = 0; d4 < 16; d4++) {
                float4 vv = vr[d4];
                acc[d4 * 4 + 0] = acc[d4 * 4 + 0] * corr + p * vv.x;
                acc[d4 * 4 + 1] = acc[d4 * 4 + 1] * corr + p * vv.y;
                acc[d4 * 4 + 2] = acc[d4 * 4 + 2] * corr + p * vv.z;
                acc[d4 * 4 + 3] = acc[d4 * 4 + 3] * corr + p * vv.w;
            }
        }
    }
    float inv = 1.0f / lsum;
    __syncthreads();
#pragma unroll
    for (int d = 0; d < 64; d++) Qs[d][tid] = acc[d] * inv;
    __syncthreads();
    for (int e = tid; e < 256 * 64; e += 256) {
        int j = e >> 6, d = e & 63;
        size_t off = (rowbase + j) * DD + colbase + d;
        bf16 h2, l2; split_bf16(Qs[d][j], h2, l2);
        oh[off] = h2; ol[off] = l2;
    }
}

// ---------------- host launch ----------------
extern "C" void kernel_launch(void* const* d_in, const int* in_sizes, int n_in,
                              void* d_out, int out_size)
{
    const float* inp   = (const float*)d_in[0];
    const float* Wq_t  = (const float*)d_in[1];
    const float* Wk_t  = (const float*)d_in[2];
    const float* Wv_t  = (const float*)d_in[3];
    const float* Wo_t  = (const float*)d_in[4];
    const float* bo_t  = (const float*)d_in[5];
    const float* Wq_s  = (const float*)d_in[6];
    const float* Wk_s  = (const float*)d_in[7];
    const float* Wv_s  = (const float*)d_in[8];
    const float* Wo_s  = (const float*)d_in[9];
    const float* bo_s  = (const float*)d_in[10];
    const float* ln_ts = (const float*)d_in[11];
    const float* ln_tb = (const float*)d_in[12];
    const float* ln_ss = (const float*)d_in[13];
    const float* ln_sb = (const float*)d_in[14];
    const float* ln2s  = (const float*)d_in[15];
    const float* ln2b  = (const float*)d_in[16];
    const float* W1    = (const float*)d_in[17];
    const float* b1    = (const float*)d_in[18];
    const float* W2    = (const float*)d_in[19];
    const float* b2    = (const float*)d_in[20];
    float* out = (float*)d_out;

    cudaFuncSetAttribute(attn_space_kernel,
                         cudaFuncAttributeMaxDynamicSharedMemorySize, SPACE_SMEM);
    cudaFuncSetAttribute(mma_gemm<0>, cudaFuncAttributeMaxDynamicSharedMemorySize, GSMEM);
    cudaFuncSetAttribute(mma_gemm<1>, cudaFuncAttributeMaxDynamicSharedMemorySize, GSMEM);
    cudaFuncSetAttribute(mma_gemm<2>, cudaFuncAttributeMaxDynamicSharedMemorySize, GSMEM);

    float *gq, *gk, *gv;
    bf16 *gxh, *gxl, *gah, *gal, *gfh, *gfl, *wth, *wtl;
    cudaGetSymbolAddress((void**)&gq, g_q);
    cudaGetSymbolAddress((void**)&gk, g_k);
    cudaGetSymbolAddress((void**)&gv, g_v);
    cudaGetSymbolAddress((void**)&gxh, g_xh);
    cudaGetSymbolAddress((void**)&gxl, g_xl);
    cudaGetSymbolAddress((void**)&gah, g_ah);
    cudaGetSymbolAddress((void**)&gal, g_al);
    cudaGetSymbolAddress((void**)&gfh, g_ffh);
    cudaGetSymbolAddress((void**)&gfl, g_ffl);
    cudaGetSymbolAddress((void**)&wth, g_wth);
    cudaGetSymbolAddress((void**)&wtl, g_wtl);

    cudaMemcpyAsync(out, inp, (size_t)NTOK * DD * sizeof(float),
                    cudaMemcpyDeviceToDevice);

    // convert + transpose + split all weights
    dim3 cb(32, 8);
    for (int lyr = 0; lyr < NLAYER; lyr++) {
        size_t wo  = (size_t)lyr * DD * DD;
        size_t w1o = (size_t)lyr * DD * FFW_;
        size_t base = (size_t)lyr * WT_LAYER;
        dim3 gdd(DD / 32, DD / 32);
        convT<<<gdd, cb>>>(Wq_t + wo, wth + base + WT_QKV_T,           wtl + base + WT_QKV_T,           DD, DD);
        convT<<<gdd, cb>>>(Wk_t + wo, wth + base + WT_QKV_T + 589824,  wtl + base + WT_QKV_T + 589824,  DD, DD);
        convT<<<gdd, cb>>>(Wv_t + wo, wth + base + WT_QKV_T + 1179648, wtl + base + WT_QKV_T + 1179648, DD, DD);
        convT<<<gdd, cb>>>(Wq_s + wo, wth + base + WT_QKV_S,           wtl + base + WT_QKV_S,           DD, DD);
        convT<<<gdd, cb>>>(Wk_s + wo, wth + base + WT_QKV_S + 589824,  wtl + base + WT_QKV_S + 589824,  DD, DD);
        convT<<<gdd, cb>>>(Wv_s + wo, wth + base + WT_QKV_S + 1179648, wtl + base + WT_QKV_S + 1179648, DD, DD);
        convT<<<gdd, cb>>>(Wo_t + wo, wth + base + WT_WO_T, wtl + base + WT_WO_T, DD, DD);
        convT<<<gdd, cb>>>(Wo_s + wo, wth + base + WT_WO_S, wtl + base + WT_WO_S, DD, DD);
        convT<<<dim3(FFW_ / 32, DD / 32), cb>>>(W1 + w1o, wth + base + WT_W1, wtl + base + WT_W1, DD, FFW_);
        convT<<<dim3(DD / 32, FFW_ / 32), cb>>>(W2 + w1o, wth + base + WT_W2, wtl + base + WT_W2, FFW_, DD);
    }

    dim3 gQKV(9, 128), gO(3, 128), gF1(12, 128), gF2(3, 128);

    for (int lyr = 0; lyr < NLAYER; lyr++) {
        size_t vo = (size_t)lyr * DD;
        size_t fo = (size_t)lyr * FFW_;
        size_t base = (size_t)lyr * WT_LAYER;

        // ---- time attention block ----
        ln_kernel<<<NTOK, 256>>>(out, ln_ts + vo, ln_tb + vo, gxh, gxl);
        mma_gemm<0><<<gQKV, 256, GSMEM>>>(gxh, gxl,
            wth + base + WT_QKV_T, wtl + base + WT_QKV_T,
            nullptr, gq, gk, gv, nullptr, nullptr, DD, 2304);
        attn_time_kernel<<<dim3(NB * LL, HH), 32>>>(gq, gk, gv, gah, gal);
        mma_gemm<2><<<gO, 256, GSMEM>>>(gah, gal,
            wth + base + WT_WO_T, wtl + base + WT_WO_T,
            bo_t + vo, out, nullptr, nullptr, nullptr, nullptr, DD, DD);

        // ---- space attention block ----
        ln_kernel<<<NTOK, 256>>>(out, ln_ss + vo, ln_sb + vo, gxh, gxl);
        mma_gemm<0><<<gQKV, 256, GSMEM>>>(gxh, gxl,
            wth + base + WT_QKV_S, wtl + base + WT_QKV_S,
            nullptr, gq, gk, gv, nullptr, nullptr, DD, 2304);
        attn_space_kernel<<<NB * TT * HH, 256, SPACE_SMEM>>>(gq, gk, gv, gah, gal);
        mma_gemm<2><<<gO, 256, GSMEM>>>(gah, gal,
            wth + base + WT_WO_S, wtl + base + WT_WO_S,
            bo_s + vo, out, nullptr, nullptr, nullptr, nullptr, DD, DD);

        // ---- FFN block ----
        ln_kernel<<<NTOK, 256>>>(out, ln2s + vo, ln2b + vo, gxh, gxl);
        mma_gemm<1><<<gF1, 256, GSMEM>>>(gxh, gxl,
            wth + base + WT_W1, wtl + base + WT_W1,
            b1 + fo, nullptr, nullptr, nullptr, gfh, gfl, DD, FFW_);
        mma_gemm<2><<<gF2, 256, GSMEM>>>(gfh, gfl,
            wth + base + WT_W2, wtl + base + WT_W2,
            b2 + vo, out, nullptr, nullptr, nullptr, nullptr, FFW_, DD);
    }
}

// round 9
// speedup vs baseline: 3.6780x; 1.0818x over previous
#include <cuda_runtime.h>
#include <cuda_bf16.h>
#include <cstdint>
#include <math.h>

#define NB 2
#define TT 32
#define LL 256
#define DD 768
#define HH 12
#define HD 64
#define FFW_ 3072
#define NLAYER 4
#define NTOK (NB*TT*LL)   // 16384

typedef __nv_bfloat16 bf16;

#if defined(__CUDA_ARCH_FEAT_SM103_ALL) || defined(__CUDA_ARCH_FEAT_SM100_ALL) || defined(__CUDA_ARCH_FEAT_SM101_ALL)
#define HAS_TCGEN05 1
#else
#define HAS_TCGEN05 0
#endif

// ---------------- scratch (device globals, no allocation) ----------------
// Packed operands are stored as SW128-swizzled 128x64 (A) / 256x64 (B) tile
// images so the GEMM producer can fetch them with single cp.async.bulk ops.
__device__ float g_q[(size_t)NTOK*DD];
__device__ float g_k[(size_t)NTOK*DD];
__device__ float g_v[(size_t)NTOK*DD];
__device__ __align__(1024) bf16  g_xh[(size_t)NTOK*DD];
__device__ __align__(1024) bf16  g_xl[(size_t)NTOK*DD];
__device__ __align__(1024) bf16  g_ah[(size_t)NTOK*DD];
__device__ __align__(1024) bf16  g_al[(size_t)NTOK*DD];
__device__ __align__(1024) bf16  g_ffh[(size_t)NTOK*FFW_];
__device__ __align__(1024) bf16  g_ffl[(size_t)NTOK*FFW_];

// transposed split weights [N,K] per layer (packed tile images)
#define WT_QKV_T 0
#define WT_QKV_S 1769472
#define WT_WO_T  3538944
#define WT_WO_S  4128768
#define WT_W1    4718592
#define WT_W2    7077888
#define WT_LAYER 9437184
__device__ __align__(1024) bf16 g_wth[(size_t)WT_LAYER*NLAYER];
__device__ __align__(1024) bf16 g_wtl[(size_t)WT_LAYER*NLAYER];

// ---------------- packed-layout helpers ----------------
// A block: 128 rows x 64 cols bf16, 128B row pitch, SW128 swizzle, 16KB/block.
// block index = (m>>7)*nck + (k>>6). Returns ELEMENT offset.
__device__ __forceinline__ size_t packA_off(int m, int k, int nck) {
    uint32_t byt = (((uint32_t)m & 127u) << 7) | (((uint32_t)k & 63u) << 1);
    uint32_t sw = byt ^ ((byt >> 3) & 0x70);
    return (((size_t)(m >> 7) * nck + (k >> 6)) << 13) + (sw >> 1);
}
// B block: 256 rows x 64 cols bf16, 32KB/block. block = (n>>8)*nck + (k>>6).
__device__ __forceinline__ size_t packB_off(int n, int k, int nck) {
    uint32_t byt = (((uint32_t)n & 255u) << 7) | (((uint32_t)k & 63u) << 1);
    uint32_t sw = byt ^ ((byt >> 3) & 0x70);
    return (((size_t)(n >> 8) * nck + (k >> 6)) << 14) + (sw >> 1);
}

// ---------------- misc helpers ----------------
__device__ __forceinline__ uint32_t smem_u32(const void* p) {
    uint32_t a;
    asm("{ .reg .u64 t; cvta.to.shared.u64 t, %1; cvt.u32.u64 %0, t; }" : "=r"(a) : "l"(p));
    return a;
}
__device__ __forceinline__ void split_bf16(float v, bf16& h, bf16& l) {
    h = __float2bfloat16(v);
    l = __float2bfloat16(v - __bfloat162float(h));
}
__device__ __forceinline__ float gelu_tanh(float x) {
    float x3 = x * x * x;
    return 0.5f * x * (1.0f + tanhf(0.7978845608028654f * (x + 0.044715f * x3)));
}

#if HAS_TCGEN05
__device__ __forceinline__ uint32_t elect_one() {
    uint32_t p;
    asm volatile("{\n\t.reg .pred p;\n\telect.sync _|p, 0xFFFFFFFF;\n\tselp.b32 %0, 1, 0, p;\n\t}" : "=r"(p));
    return p;
}
__device__ __forceinline__ void mbar_init(uint32_t a, uint32_t c) {
    asm volatile("mbarrier.init.shared.b64 [%0], %1;" :: "r"(a), "r"(c) : "memory");
}
__device__ __forceinline__ void mbar_inval(uint32_t a) {
    asm volatile("mbarrier.inval.shared.b64 [%0];" :: "r"(a) : "memory");
}
__device__ __forceinline__ void mbar_wait(uint32_t a, uint32_t ph) {
    uint32_t done = 0;
    while (!done) {
        asm volatile(
            "{\n\t.reg .pred p;\n\t"
            "mbarrier.try_wait.parity.acquire.cta.shared::cta.b64 p, [%1], %2, 0x989680;\n\t"
            "selp.b32 %0, 1, 0, p;\n\t}"
            : "=r"(done) : "r"(a), "r"(ph) : "memory");
    }
}
__device__ __forceinline__ void mbar_expect_tx(uint32_t a, uint32_t bytes) {
    asm volatile("mbarrier.arrive.expect_tx.shared.b64 _, [%0], %1;"
                 :: "r"(a), "r"(bytes) : "memory");
}
__device__ __forceinline__ void bulk_ld(uint32_t dst, const void* src, uint32_t bytes,
                                        uint32_t mbar) {
    asm volatile(
        "cp.async.bulk.shared::cta.global.mbarrier::complete_tx::bytes [%0], [%1], %2, [%3];"
        :: "r"(dst), "l"(src), "r"(bytes), "r"(mbar) : "memory");
}
__device__ __forceinline__ void tm_alloc(uint32_t dst, uint32_t n) {
    asm volatile("tcgen05.alloc.cta_group::1.sync.aligned.shared::cta.b32 [%0], %1;"
                 :: "r"(dst), "r"(n) : "memory");
}
__device__ __forceinline__ void tm_relinq() {
    asm volatile("tcgen05.relinquish_alloc_permit.cta_group::1.sync.aligned;");
}
__device__ __forceinline__ void tm_dealloc(uint32_t t, uint32_t n) {
    asm volatile("tcgen05.dealloc.cta_group::1.sync.aligned.b32 %0, %1;" :: "r"(t), "r"(n));
}
__device__ __forceinline__ void tm_commit(uint32_t mbar) {
    asm volatile("tcgen05.commit.cta_group::1.mbarrier::arrive::one.shared::cluster.b64 [%0];"
                 :: "r"(mbar) : "memory");
}
__device__ __forceinline__ void mma_f16_ss(uint32_t d, uint64_t a, uint64_t b,
                                           uint32_t idesc, uint32_t en) {
    asm volatile(
        "{\n\t.reg .pred p;\n\tsetp.ne.u32 p, %4, 0;\n\t"
        "tcgen05.mma.cta_group::1.kind::f16 [%0], %1, %2, %3, {%5, %5, %5, %5}, p;\n\t}"
        :: "r"(d), "l"(a), "l"(b), "r"(idesc), "r"(en), "r"(0u) : "memory");
}
__device__ __forceinline__ uint64_t mkdesc(uint32_t addr) {
    return (((uint64_t)2 << 61) | ((uint64_t)1 << 46) | ((uint64_t)64 << 32) |
            ((uint64_t)1 << 16)) | (uint64_t)((addr >> 4) & 0x3FFF);
}
#define LDTM_X32(r, a) \
    asm volatile( \
        "tcgen05.ld.sync.aligned.32x32b.x32.b32 " \
        "{%0, %1, %2, %3, %4, %5, %6, %7, " \
        " %8, %9, %10, %11, %12, %13, %14, %15, " \
        " %16, %17, %18, %19, %20, %21, %22, %23, " \
        " %24, %25, %26, %27, %28, %29, %30, %31}, [%32];" \
        : "=r"((r)[0]),  "=r"((r)[1]),  "=r"((r)[2]),  "=r"((r)[3]), \
          "=r"((r)[4]),  "=r"((r)[5]),  "=r"((r)[6]),  "=r"((r)[7]), \
          "=r"((r)[8]),  "=r"((r)[9]),  "=r"((r)[10]), "=r"((r)[11]), \
          "=r"((r)[12]), "=r"((r)[13]), "=r"((r)[14]), "=r"((r)[15]), \
          "=r"((r)[16]), "=r"((r)[17]), "=r"((r)[18]), "=r"((r)[19]), \
          "=r"((r)[20]), "=r"((r)[21]), "=r"((r)[22]), "=r"((r)[23]), \
          "=r"((r)[24]), "=r"((r)[25]), "=r"((r)[26]), "=r"((r)[27]), \
          "=r"((r)[28]), "=r"((r)[29]), "=r"((r)[30]), "=r"((r)[31]) \
        : "r"(a))
#endif

// ---------------- weight convert + transpose + bf16 split (packed out) ----------------
__global__ void convT(const float* __restrict__ W, bf16* __restrict__ th,
                      bf16* __restrict__ tl, int K, int N)
{
    __shared__ float t[32][33];
    int n0 = blockIdx.x * 32, k0 = blockIdx.y * 32;
    int tx = threadIdx.x, ty = threadIdx.y; // (32,8)
    int nck = K >> 6;
#pragma unroll
    for (int r = 0; r < 4; r++) {
        int k = k0 + ty + r * 8;
        t[ty + r * 8][tx] = W[(size_t)k * N + n0 + tx];
    }
    __syncthreads();
#pragma unroll
    for (int r = 0; r < 4; r++) {
        int n = n0 + ty + r * 8;
        float v = t[tx][ty + r * 8];
        bf16 h, l; split_bf16(v, h, l);
        size_t o = packB_off(n, k0 + tx, nck);
        th[o] = h;
        tl[o] = l;
    }
}

// ---------------- LayerNorm -> split bf16 (packed out) ----------------
__global__ void ln_kernel(const float* __restrict__ h, const float* __restrict__ sc,
                          const float* __restrict__ bi,
                          bf16* __restrict__ xh, bf16* __restrict__ xl)
{
    int row = blockIdx.x;
    const float* hr = h + (size_t)row * DD;
    int tid = threadIdx.x;
    float v0 = hr[tid], v1 = hr[tid + 256], v2 = hr[tid + 512];
    __shared__ float red[256];
    red[tid] = v0 + v1 + v2;
    __syncthreads();
    for (int o = 128; o > 0; o >>= 1) {
        if (tid < o) red[tid] += red[tid + o];
        __syncthreads();
    }
    float mean = red[0] * (1.0f / DD);
    __syncthreads();
    float d0 = v0 - mean, d1 = v1 - mean, d2 = v2 - mean;
    red[tid] = d0 * d0 + d1 * d1 + d2 * d2;
    __syncthreads();
    for (int o = 128; o > 0; o >>= 1) {
        if (tid < o) red[tid] += red[tid + o];
        __syncthreads();
    }
    float rstd = rsqrtf(red[0] * (1.0f / DD) + 1e-5f);
    float y0 = d0 * rstd * sc[tid]       + bi[tid];
    float y1 = d1 * rstd * sc[tid + 256] + bi[tid + 256];
    float y2 = d2 * rstd * sc[tid + 512] + bi[tid + 512];
    bf16 hh, ll;
    size_t o0 = packA_off(row, tid,       12);
    size_t o1 = packA_off(row, tid + 256, 12);
    size_t o2 = packA_off(row, tid + 512, 12);
    split_bf16(y0, hh, ll); xh[o0] = hh; xl[o0] = ll;
    split_bf16(y1, hh, ll); xh[o1] = hh; xl[o1] = ll;
    split_bf16(y2, hh, ll); xh[o2] = hh; xl[o2] = ll;
}

// ---------------- tcgen05 GEMM: C[M,Nc] = A[M,Kd] @ B[Nc,Kd]^T ----------------
// bf16x3 split: Ah*Bh + Al*Bh + Ah*Bl, fp32 accum in TMEM.
// Tile 128x256, double-buffered 96KB stages fed by cp.async.bulk from packed
// gmem tile images; warp-specialized producer (warp0) / MMA issuer (warp1).
// EPI 0: packed QKV store to C0/C1/C2 fp32 (each stride 768)
// EPI 1: gelu(acc + bias) -> split bf16 Oh/Ol (packed A-layout, nck=Nc/64)
// EPI 2: C0 += acc + bias (fp32 residual)
#define GSMEM 197632
#define STAGE_BYTES 98304

template <int EPI>
__global__ void __launch_bounds__(256) mma_gemm(
    const bf16* __restrict__ Ah, const bf16* __restrict__ Al,
    const bf16* __restrict__ Bh, const bf16* __restrict__ Bl,
    const float* __restrict__ bias,
    float* __restrict__ C0, float* __restrict__ C1, float* __restrict__ C2,
    bf16* __restrict__ Oh, bf16* __restrict__ Ol,
    int Kd, int Nc)
{
#if HAS_TCGEN05
    extern __shared__ char sm[];
    const uint32_t smem_base = smem_u32(sm);
    const int tid = threadIdx.x;
    const int bm = blockIdx.y * 128;
    const int bn = blockIdx.x * 256;
    const int NC = Kd >> 6;

    // barriers: full0 @8, full1 @16, free0 @24, free1 @32, done @40
    if (tid == 0) {
        mbar_init(smem_base + 8, 1);
        mbar_init(smem_base + 16, 1);
        mbar_init(smem_base + 24, 1);
        mbar_init(smem_base + 32, 1);
        mbar_init(smem_base + 40, 1);
    }
    if (tid < 32) { tm_alloc(smem_base, 256); tm_relinq(); }
    __syncthreads();
    uint32_t tmem;
    asm volatile("ld.shared.b32 %0, [%1];" : "=r"(tmem) : "r"(smem_base));

    const uint32_t IDESC = (1u << 4) | (1u << 7) | (1u << 10) |
                           ((256u / 8) << 17) | ((128u / 16) << 24);

    if (tid < 32 && elect_one()) {
        // ---- producer: 4 bulk copies per chunk from packed gmem ----
        const char* pAh = (const char*)(Ah + ((size_t)blockIdx.y * NC << 13));
        const char* pAl = (const char*)(Al + ((size_t)blockIdx.y * NC << 13));
        const char* pBh = (const char*)(Bh + ((size_t)blockIdx.x * NC << 14));
        const char* pBl = (const char*)(Bl + ((size_t)blockIdx.x * NC << 14));
        uint32_t fr0 = 0, fr1 = 0;
        for (int c = 0; c < NC; c++) {
            const int s = c & 1;
            if (c >= 2) {
                if (s == 0) { mbar_wait(smem_base + 24, fr0); fr0 ^= 1; }
                else        { mbar_wait(smem_base + 32, fr1); fr1 ^= 1; }
            }
            const uint32_t su = smem_base + 1024 + (uint32_t)s * STAGE_BYTES;
            const uint32_t fb = smem_base + 8 + 8 * s;
            mbar_expect_tx(fb, STAGE_BYTES);
            bulk_ld(su,          pAh + ((size_t)c << 14), 16384, fb);
            bulk_ld(su + 16384,  pAl + ((size_t)c << 14), 16384, fb);
            bulk_ld(su + 32768,  pBh + ((size_t)c << 15), 32768, fb);
            bulk_ld(su + 65536,  pBl + ((size_t)c << 15), 32768, fb);
        }
    } else if (tid >= 32 && tid < 64 && elect_one()) {
        // ---- consumer: wait stage full, issue 36 MMAs, release stage ----
        uint32_t fp0 = 0, fp1 = 0;
        for (int c = 0; c < NC; c++) {
            const int s = c & 1;
            if (s == 0) { mbar_wait(smem_base + 8, fp0); fp0 ^= 1; }
            else        { mbar_wait(smem_base + 16, fp1); fp1 ^= 1; }
            const uint32_t su = smem_base + 1024 + (uint32_t)s * STAGE_BYTES;
            uint64_t dAh = mkdesc(su);
            uint64_t dAl = mkdesc(su + 16384);
            uint64_t dBh = mkdesc(su + 32768);
            uint64_t dBl = mkdesc(su + 65536);
#pragma unroll
            for (int ks = 0; ks < 4; ks++)
                mma_f16_ss(tmem, dAh + ks * 2, dBh + ks * 2, IDESC, (c > 0) | (ks > 0));
#pragma unroll
            for (int ks = 0; ks < 4; ks++)
                mma_f16_ss(tmem, dAl + ks * 2, dBh + ks * 2, IDESC, 1);
#pragma unroll
            for (int ks = 0; ks < 4; ks++)
                mma_f16_ss(tmem, dAh + ks * 2, dBl + ks * 2, IDESC, 1);
            tm_commit(smem_base + 24 + 8 * s);
        }
        tm_commit(smem_base + 40);   // all MMAs complete -> done
    }

    // all threads: wait for full accumulation
    mbar_wait(smem_base + 40, 0);
    asm volatile("tcgen05.fence::after_thread_sync;" ::: "memory");

    // stage D through smem (transposed-coalesced writeout)
    const int w = tid >> 5, lane = tid & 31;
    const int cb = (w >> 2) * 128;
    const int r = (w & 3) * 32 + lane;
    float* Cs = (float*)(sm + 1024);
#pragma unroll
    for (int cc = 0; cc < 4; cc++) {
        uint32_t regs[32];
        LDTM_X32(regs, tmem + cb + cc * 32);
        asm volatile("tcgen05.wait::ld.sync.aligned;" ::: "memory");
#pragma unroll
        for (int j = 0; j < 32; j++)
            Cs[r * 257 + cb + cc * 32 + j] = __uint_as_float(regs[j]);
    }
    asm volatile("tcgen05.fence::before_thread_sync;" ::: "memory");
    __syncthreads();

    if (EPI == 0) {
        float* dst; int nb = bn;
        if (nb < 768) dst = C0;
        else if (nb < 1536) { dst = C1; nb -= 768; }
        else { dst = C2; nb -= 1536; }
#pragma unroll 4
        for (int it = 0; it < 128; it++)
            dst[(size_t)(bm + it) * 768 + nb + tid] = Cs[it * 257 + tid];
    } else if (EPI == 1) {
        float bb = bias[bn + tid];
        const int nck = Nc >> 6;
#pragma unroll 4
        for (int it = 0; it < 128; it++) {
            float g = gelu_tanh(Cs[it * 257 + tid] + bb);
            bf16 h, l; split_bf16(g, h, l);
            size_t o = packA_off(bm + it, bn + tid, nck);
            Oh[o] = h; Ol[o] = l;
        }
    } else {
        float bb = bias[bn + tid];
#pragma unroll 4
        for (int it = 0; it < 128; it++) {
            size_t o = (size_t)(bm + it) * Nc + bn + tid;
            C0[o] += Cs[it * 257 + tid] + bb;
        }
    }
    __syncthreads();
    if (tid == 0) {
        mbar_inval(smem_base + 8);  mbar_inval(smem_base + 16);
        mbar_inval(smem_base + 24); mbar_inval(smem_base + 32);
        mbar_inval(smem_base + 40);
    }
    if (tid < 32) tm_dealloc(tmem, 256);
#else
    // correct-but-slow fallback for the non-arch-specific compile pass
    const int tid = threadIdx.x;
    const int bm = blockIdx.y * 128;
    const int bn = blockIdx.x * 256;
    const int nck = Kd >> 6;
    for (int e = tid; e < 128 * 256; e += 256) {
        int r = e >> 8, c = e & 255;
        float s = 0.f;
        for (int k = 0; k < Kd; k++) {
            size_t ao = packA_off(bm + r, k, nck);
            size_t bo = packB_off(bn + c, k, nck);
            float a = __bfloat162float(Ah[ao]) + __bfloat162float(Al[ao]);
            float b = __bfloat162float(Bh[bo]) + __bfloat162float(Bl[bo]);
            s += a * b;
        }
        if (EPI == 0) {
            float* dst; int nb = bn + c;
            if (nb < 768) dst = C0;
            else if (nb < 1536) { dst = C1; nb -= 768; }
            else { dst = C2; nb -= 1536; }
            dst[(size_t)(bm + r) * 768 + nb] = s;
        } else if (EPI == 1) {
            float g = gelu_tanh(s + bias[bn + c]);
            bf16 h, l; split_bf16(g, h, l);
            size_t o = packA_off(bm + r, bn + c, Nc >> 6);
            Oh[o] = h; Ol[o] = l;
        } else {
            size_t o = (size_t)(bm + r) * Nc + bn + c;
            C0[o] += s + bias[bn + c];
        }
    }
#endif
}

// ---------------- Time attention (T=32), packed bf16 out ----------------
__global__ void __launch_bounds__(32) attn_time_kernel(
    const float* __restrict__ q, const float* __restrict__ k,
    const float* __restrict__ v, bf16* __restrict__ oh, bf16* __restrict__ ol)
{
    __shared__ float Ks[32][64];
    __shared__ float Vs[32][64];
    __shared__ float Qs[64][33];
    int bl = blockIdx.x;
    int h = blockIdx.y;
    int b = bl / LL, l = bl % LL;
    int tid = threadIdx.x;
    size_t colbase = (size_t)h * HD;

    for (int e = tid; e < 32 * 64; e += 32) {
        int j = e >> 6, d = e & 63;
        size_t off = ((size_t)(b * TT + j) * LL + l) * DD + colbase + d;
        Ks[j][d] = k[off];
        Vs[j][d] = v[off];
        Qs[d][j] = q[off];
    }
    __syncwarp();

    float qr[64];
#pragma unroll
    for (int d = 0; d < 64; d++) qr[d] = Qs[d][tid];

    float sc_[32];
#pragma unroll 4
    for (int j = 0; j < 32; j++) {
        float s = 0.f;
        const float4* kr = (const float4*)Ks[j];
#pragma unroll
        for (int d4 = 0; d4 < 16; d4++) {
            float4 kk = kr[d4];
            s += qr[d4 * 4 + 0] * kk.x + qr[d4 * 4 + 1] * kk.y
               + qr[d4 * 4 + 2] * kk.z + qr[d4 * 4 + 3] * kk.w;
        }
        sc_[j] = s * 0.125f;
    }
    float m = sc_[0];
#pragma unroll
    for (int j = 1; j < 32; j++) m = fmaxf(m, sc_[j]);
    float lsum = 0.f;
#pragma unroll
    for (int j = 0; j < 32; j++) { sc_[j] = __expf(sc_[j] - m); lsum += sc_[j]; }
    float inv = 1.0f / lsum;

#pragma unroll
    for (int d4 = 0; d4 < 16; d4++) {
        float ax = 0.f, ay = 0.f, az = 0.f, aw = 0.f;
#pragma unroll
        for (int j = 0; j < 32; j++) {
            float4 vv = ((const float4*)Vs[j])[d4];
            float w = sc_[j];
            ax += w * vv.x; ay += w * vv.y; az += w * vv.z; aw += w * vv.w;
        }
        Qs[d4 * 4 + 0][tid] = ax * inv;
        Qs[d4 * 4 + 1][tid] = ay * inv;
        Qs[d4 * 4 + 2][tid] = az * inv;
        Qs[d4 * 4 + 3][tid] = aw * inv;
    }
    __syncwarp();
    for (int e = tid; e < 32 * 64; e += 32) {
        int j = e >> 6, d = e & 63;
        int mtok = (b * TT + j) * LL + l;
        bf16 h2, l2; split_bf16(Qs[d][j], h2, l2);
        size_t o = packA_off(mtok, (int)colbase + d, 12);
        oh[o] = h2; ol[o] = l2;
    }
}

// ---------------- Space attention (L=256), packed bf16 out ----------------
#define SPACE_SMEM ((64 * 257 + 64 * 64 + 64 * 64) * 4)
__global__ void __launch_bounds__(256) attn_space_kernel(
    const float* __restrict__ q, const float* __restrict__ k,
    const float* __restrict__ v, bf16* __restrict__ oh, bf16* __restrict__ ol)
{
    extern __shared__ float smf[];
    float(*Qs)[257] = (float(*)[257])smf;
    float* Ks = smf + 64 * 257;
    float* Vs = Ks + 64 * 64;
    int gid = blockIdx.x;
    int h = gid % HH;
    int bt = gid / HH;
    int tid = threadIdx.x;
    size_t rowbase = (size_t)bt * LL;
    size_t colbase = (size_t)h * HD;

    for (int e = tid; e < 256 * 64; e += 256) {
        int j = e >> 6, d = e & 63;
        Qs[d][j] = q[(rowbase + j) * DD + colbase + d];
    }
    __syncthreads();

    float qr[64];
#pragma unroll
    for (int d = 0; d < 64; d++) qr[d] = Qs[d][tid];

    float m = -1e30f, lsum = 0.f;
    float acc[64];
#pragma unroll
    for (int d = 0; d < 64; d++) acc[d] = 0.f;

    for (int c0 = 0; c0 < LL; c0 += 64) {
        __syncthreads();
        for (int e = tid; e < 64 * 64; e += 256) {
            int j = e >> 6, d = e & 63;
            size_t off = (rowbase + c0 + j) * DD + colbase + d;
            Ks[e] = k[off];
            Vs[e] = v[off];
        }
        __syncthreads();
        for (int j = 0; j < 64; j++) {
            float s = 0.f;
            const float4* kr = (const float4*)(Ks + j * 64);
#pragma unroll
            for (int d4 = 0; d4 < 16; d4++) {
                float4 kk = kr[d4];
                s += qr[d4 * 4 + 0] * kk.x + qr[d4 * 4 + 1] * kk.y
                   + qr[d4 * 4 + 2] * kk.z + qr[d4 * 4 + 3] * kk.w;
            }
            s *= 0.125f;
            float mn = fmaxf(m, s);
            float corr = __expf(m - mn);
            float p = __expf(s - mn);
            lsum = lsum * corr + p;
            m = mn;
            const float4* vr = (const float4*)(Vs + j * 64);
#pragma unroll
            for (int d4 = 0; d4 < 16; d4++) {
                float4 vv = vr[d4];
                acc[d4 * 4 + 0] = acc[d4 * 4 + 0] * corr + p * vv.x;
                acc[d4 * 4 + 1] = acc[d4 * 4 + 1] * corr + p * vv.y;
                acc[d4 * 4 + 2] = acc[d4 * 4 + 2] * corr + p * vv.z;
                acc[d4 * 4 + 3] = acc[d4 * 4 + 3] * corr + p * vv.w;
            }
        }
    }
    float inv = 1.0f / lsum;
    __syncthreads();
#pragma unroll
    for (int d = 0; d < 64; d++) Qs[d][tid] = acc[d] * inv;
    __syncthreads();
    for (int e = tid; e < 256 * 64; e += 256) {
        int j = e >> 6, d = e & 63;
        int mtok = (int)rowbase + j;
        bf16 h2, l2; split_bf16(Qs[d][j], h2, l2);
        size_t o = packA_off(mtok, (int)colbase + d, 12);
        oh[o] = h2; ol[o] = l2;
    }
}

// ---------------- host launch ----------------
extern "C" void kernel_launch(void* const* d_in, const int* in_sizes, int n_in,
                              void* d_out, int out_size)
{
    const float* inp   = (const float*)d_in[0];
    const float* Wq_t  = (const float*)d_in[1];
    const float* Wk_t  = (const float*)d_in[2];
    const float* Wv_t  = (const float*)d_in[3];
    const float* Wo_t  = (const float*)d_in[4];
    const float* bo_t  = (const float*)d_in[5];
    const float* Wq_s  = (const float*)d_in[6];
    const float* Wk_s  = (const float*)d_in[7];
    const float* Wv_s  = (const float*)d_in[8];
    const float* Wo_s  = (const float*)d_in[9];
    const float* bo_s  = (const float*)d_in[10];
    const float* ln_ts = (const float*)d_in[11];
    const float* ln_tb = (const float*)d_in[12];
    const float* ln_ss = (const float*)d_in[13];
    const float* ln_sb = (const float*)d_in[14];
    const float* ln2s  = (const float*)d_in[15];
    const float* ln2b  = (const float*)d_in[16];
    const float* W1    = (const float*)d_in[17];
    const float* b1    = (const float*)d_in[18];
    const float* W2    = (const float*)d_in[19];
    const float* b2    = (const float*)d_in[20];
    float* out = (float*)d_out;

    cudaFuncSetAttribute(attn_space_kernel,
                         cudaFuncAttributeMaxDynamicSharedMemorySize, SPACE_SMEM);
    cudaFuncSetAttribute(mma_gemm<0>, cudaFuncAttributeMaxDynamicSharedMemorySize, GSMEM);
    cudaFuncSetAttribute(mma_gemm<1>, cudaFuncAttributeMaxDynamicSharedMemorySize, GSMEM);
    cudaFuncSetAttribute(mma_gemm<2>, cudaFuncAttributeMaxDynamicSharedMemorySize, GSMEM);

    float *gq, *gk, *gv;
    bf16 *gxh, *gxl, *gah, *gal, *gfh, *gfl, *wth, *wtl;
    cudaGetSymbolAddress((void**)&gq, g_q);
    cudaGetSymbolAddress((void**)&gk, g_k);
    cudaGetSymbolAddress((void**)&gv, g_v);
    cudaGetSymbolAddress((void**)&gxh, g_xh);
    cudaGetSymbolAddress((void**)&gxl, g_xl);
    cudaGetSymbolAddress((void**)&gah, g_ah);
    cudaGetSymbolAddress((void**)&gal, g_al);
    cudaGetSymbolAddress((void**)&gfh, g_ffh);
    cudaGetSymbolAddress((void**)&gfl, g_ffl);
    cudaGetSymbolAddress((void**)&wth, g_wth);
    cudaGetSymbolAddress((void**)&wtl, g_wtl);

    cudaMemcpyAsync(out, inp, (size_t)NTOK * DD * sizeof(float),
                    cudaMemcpyDeviceToDevice);

    // convert + transpose + split all weights into packed tile images
    dim3 cb(32, 8);
    for (int lyr = 0; lyr < NLAYER; lyr++) {
        size_t wo  = (size_t)lyr * DD * DD;
        size_t w1o = (size_t)lyr * DD * FFW_;
        size_t base = (size_t)lyr * WT_LAYER;
        dim3 gdd(DD / 32, DD / 32);
        convT<<<gdd, cb>>>(Wq_t + wo, wth + base + WT_QKV_T,           wtl + base + WT_QKV_T,           DD, DD);
        convT<<<gdd, cb>>>(Wk_t + wo, wth + base + WT_QKV_T + 589824,  wtl + base + WT_QKV_T + 589824,  DD, DD);
        convT<<<gdd, cb>>>(Wv_t + wo, wth + base + WT_QKV_T + 1179648, wtl + base + WT_QKV_T + 1179648, DD, DD);
        convT<<<gdd, cb>>>(Wq_s + wo, wth + base + WT_QKV_S,           wtl + base + WT_QKV_S,           DD, DD);
        convT<<<gdd, cb>>>(Wk_s + wo, wth + base + WT_QKV_S + 589824,  wtl + base + WT_QKV_S + 589824,  DD, DD);
        convT<<<gdd, cb>>>(Wv_s + wo, wth + base + WT_QKV_S + 1179648, wtl + base + WT_QKV_S + 1179648, DD, DD);
        convT<<<gdd, cb>>>(Wo_t + wo, wth + base + WT_WO_T, wtl + base + WT_WO_T, DD, DD);
        convT<<<gdd, cb>>>(Wo_s + wo, wth + base + WT_WO_S, wtl + base + WT_WO_S, DD, DD);
        convT<<<dim3(FFW_ / 32, DD / 32), cb>>>(W1 + w1o, wth + base + WT_W1, wtl + base + WT_W1, DD, FFW_);
        convT<<<dim3(DD / 32, FFW_ / 32), cb>>>(W2 + w1o, wth + base + WT_W2, wtl + base + WT_W2, FFW_, DD);
    }

    dim3 gQKV(9, 128), gO(3, 128), gF1(12, 128), gF2(3, 128);

    for (int lyr = 0; lyr < NLAYER; lyr++) {
        size_t vo = (size_t)lyr * DD;
        size_t fo = (size_t)lyr * FFW_;
        size_t base = (size_t)lyr * WT_LAYER;

        // ---- time attention block ----
        ln_kernel<<<NTOK, 256>>>(out, ln_ts + vo, ln_tb + vo, gxh, gxl);
        mma_gemm<0><<<gQKV, 256, GSMEM>>>(gxh, gxl,
            wth + base + WT_QKV_T, wtl + base + WT_QKV_T,
            nullptr, gq, gk, gv, nullptr, nullptr, DD, 2304);
        attn_time_kernel<<<dim3(NB * LL, HH), 32>>>(gq, gk, gv, gah, gal);
        mma_gemm<2><<<gO, 256, GSMEM>>>(gah, gal,
            wth + base + WT_WO_T, wtl + base + WT_WO_T,
            bo_t + vo, out, nullptr, nullptr, nullptr, nullptr, DD, DD);

        // ---- space attention block ----
        ln_kernel<<<NTOK, 256>>>(out, ln_ss + vo, ln_sb + vo, gxh, gxl);
        mma_gemm<0><<<gQKV, 256, GSMEM>>>(gxh, gxl,
            wth + base + WT_QKV_S, wtl + base + WT_QKV_S,
            nullptr, gq, gk, gv, nullptr, nullptr, DD, 2304);
        attn_space_kernel<<<NB * TT * HH, 256, SPACE_SMEM>>>(gq, gk, gv, gah, gal);
        mma_gemm<2><<<gO, 256, GSMEM>>>(gah, gal,
            wth + base + WT_WO_S, wtl + base + WT_WO_S,
            bo_s + vo, out, nullptr, nullptr, nullptr, nullptr, DD, DD);

        // ---- FFN block ----
        ln_kernel<<<NTOK, 256>>>(out, ln2s + vo, ln2b + vo, gxh, gxl);
        mma_gemm<1><<<gF1, 256, GSMEM>>>(gxh, gxl,
            wth + base + WT_W1, wtl + base + WT_W1,
            b1 + fo, nullptr, nullptr, nullptr, gfh, gfl, DD, FFW_);
        mma_gemm<2><<<gF2, 256, GSMEM>>>(gfh, gfl,
            wth + base + WT_W2, wtl + base + WT_W2,
            b2 + vo, out, nullptr, nullptr, nullptr, nullptr, FFW_, DD);
    }
}

// round 11
// speedup vs baseline: 4.0472x; 1.1004x over previous
#include <cuda_runtime.h>
#include <cuda_bf16.h>
#include <cuda_fp16.h>
#include <cstdint>
#include <math.h>

#define NB 2
#define TT 32
#define LL 256
#define DD 768
#define HH 12
#define HD 64
#define FFW_ 3072
#define NLAYER 4
#define NTOK (NB*TT*LL)   // 16384

typedef __half fp16;

#if defined(__CUDA_ARCH_FEAT_SM103_ALL) || defined(__CUDA_ARCH_FEAT_SM100_ALL) || defined(__CUDA_ARCH_FEAT_SM101_ALL)
#define HAS_TCGEN05 1
#else
#define HAS_TCGEN05 0
#endif

// ---------------- scratch (device globals, no allocation) ----------------
// Packed operands stored as SW128-swizzled 128x64 (A) / 256x64 (B) tile
// images so the GEMM producer fetches them with single cp.async.bulk ops.
__device__ float g_q[(size_t)NTOK*DD];
__device__ float g_k[(size_t)NTOK*DD];
__device__ float g_v[(size_t)NTOK*DD];
__device__ __align__(1024) fp16  g_xh[(size_t)NTOK*DD];
__device__ __align__(1024) fp16  g_xl[(size_t)NTOK*DD];
__device__ __align__(1024) fp16  g_ah[(size_t)NTOK*DD];
__device__ __align__(1024) fp16  g_al[(size_t)NTOK*DD];
__device__ __align__(1024) fp16  g_ffh[(size_t)NTOK*FFW_];
__device__ __align__(1024) fp16  g_ffl[(size_t)NTOK*FFW_];

// transposed fp16 weights [N,K] per layer (packed tile images)
#define WT_QKV_T 0
#define WT_QKV_S 1769472
#define WT_WO_T  3538944
#define WT_WO_S  4128768
#define WT_W1    4718592
#define WT_W2    7077888
#define WT_LAYER 9437184
__device__ __align__(1024) fp16 g_wth[(size_t)WT_LAYER*NLAYER];

// ---------------- packed-layout helpers ----------------
__device__ __forceinline__ size_t packA_off(int m, int k, int nck) {
    uint32_t byt = (((uint32_t)m & 127u) << 7) | (((uint32_t)k & 63u) << 1);
    uint32_t sw = byt ^ ((byt >> 3) & 0x70);
    return (((size_t)(m >> 7) * nck + (k >> 6)) << 13) + (sw >> 1);
}
__device__ __forceinline__ size_t packB_off(int n, int k, int nck) {
    uint32_t byt = (((uint32_t)n & 255u) << 7) | (((uint32_t)k & 63u) << 1);
    uint32_t sw = byt ^ ((byt >> 3) & 0x70);
    return (((size_t)(n >> 8) * nck + (k >> 6)) << 14) + (sw >> 1);
}

// ---------------- misc helpers ----------------
__device__ __forceinline__ uint32_t smem_u32(const void* p) {
    uint32_t a;
    asm("{ .reg .u64 t; cvta.to.shared.u64 t, %1; cvt.u32.u64 %0, t; }" : "=r"(a) : "l"(p));
    return a;
}
__device__ __forceinline__ void split_f16(float v, fp16& h, fp16& l) {
    h = __float2half_rn(v);
    l = __float2half_rn(v - __half2float(h));
}
__device__ __forceinline__ float gelu_tanh(float x) {
    float x3 = x * x * x;
    return 0.5f * x * (1.0f + tanhf(0.7978845608028654f * (x + 0.044715f * x3)));
}

#if HAS_TCGEN05
__device__ __forceinline__ uint32_t elect_one() {
    uint32_t p;
    asm volatile("{\n\t.reg .pred p;\n\telect.sync _|p, 0xFFFFFFFF;\n\tselp.b32 %0, 1, 0, p;\n\t}" : "=r"(p));
    return p;
}
__device__ __forceinline__ void mbar_init(uint32_t a, uint32_t c) {
    asm volatile("mbarrier.init.shared.b64 [%0], %1;" :: "r"(a), "r"(c) : "memory");
}
__device__ __forceinline__ void mbar_inval(uint32_t a) {
    asm volatile("mbarrier.inval.shared.b64 [%0];" :: "r"(a) : "memory");
}
__device__ __forceinline__ void mbar_wait(uint32_t a, uint32_t ph) {
    uint32_t done = 0;
    while (!done) {
        asm volatile(
            "{\n\t.reg .pred p;\n\t"
            "mbarrier.try_wait.parity.acquire.cta.shared::cta.b64 p, [%1], %2, 0x989680;\n\t"
            "selp.b32 %0, 1, 0, p;\n\t}"
            : "=r"(done) : "r"(a), "r"(ph) : "memory");
    }
}
__device__ __forceinline__ void mbar_expect_tx(uint32_t a, uint32_t bytes) {
    asm volatile("mbarrier.arrive.expect_tx.shared.b64 _, [%0], %1;"
                 :: "r"(a), "r"(bytes) : "memory");
}
__device__ __forceinline__ void bulk_ld(uint32_t dst, const void* src, uint32_t bytes,
                                        uint32_t mbar) {
    asm volatile(
        "cp.async.bulk.shared::cta.global.mbarrier::complete_tx::bytes [%0], [%1], %2, [%3];"
        :: "r"(dst), "l"(src), "r"(bytes), "r"(mbar) : "memory");
}
__device__ __forceinline__ void tm_alloc(uint32_t dst, uint32_t n) {
    asm volatile("tcgen05.alloc.cta_group::1.sync.aligned.shared::cta.b32 [%0], %1;"
                 :: "r"(dst), "r"(n) : "memory");
}
__device__ __forceinline__ void tm_relinq() {
    asm volatile("tcgen05.relinquish_alloc_permit.cta_group::1.sync.aligned;");
}
__device__ __forceinline__ void tm_dealloc(uint32_t t, uint32_t n) {
    asm volatile("tcgen05.dealloc.cta_group::1.sync.aligned.b32 %0, %1;" :: "r"(t), "r"(n));
}
__device__ __forceinline__ void tm_commit(uint32_t mbar) {
    asm volatile("tcgen05.commit.cta_group::1.mbarrier::arrive::one.shared::cluster.b64 [%0];"
                 :: "r"(mbar) : "memory");
}
__device__ __forceinline__ void mma_f16_ss(uint32_t d, uint64_t a, uint64_t b,
                                           uint32_t idesc, uint32_t en) {
    asm volatile(
        "{\n\t.reg .pred p;\n\tsetp.ne.u32 p, %4, 0;\n\t"
        "tcgen05.mma.cta_group::1.kind::f16 [%0], %1, %2, %3, {%5, %5, %5, %5}, p;\n\t}"
        :: "r"(d), "l"(a), "l"(b), "r"(idesc), "r"(en), "r"(0u) : "memory");
}
__device__ __forceinline__ uint64_t mkdesc(uint32_t addr) {
    return (((uint64_t)2 << 61) | ((uint64_t)1 << 46) | ((uint64_t)64 << 32) |
            ((uint64_t)1 << 16)) | (uint64_t)((addr >> 4) & 0x3FFF);
}
#define LDTM_X32(r, a) \
    asm volatile( \
        "tcgen05.ld.sync.aligned.32x32b.x32.b32 " \
        "{%0, %1, %2, %3, %4, %5, %6, %7, " \
        " %8, %9, %10, %11, %12, %13, %14, %15, " \
        " %16, %17, %18, %19, %20, %21, %22, %23, " \
        " %24, %25, %26, %27, %28, %29, %30, %31}, [%32];" \
        : "=r"((r)[0]),  "=r"((r)[1]),  "=r"((r)[2]),  "=r"((r)[3]), \
          "=r"((r)[4]),  "=r"((r)[5]),  "=r"((r)[6]),  "=r"((r)[7]), \
          "=r"((r)[8]),  "=r"((r)[9]),  "=r"((r)[10]), "=r"((r)[11]), \
          "=r"((r)[12]), "=r"((r)[13]), "=r"((r)[14]), "=r"((r)[15]), \
          "=r"((r)[16]), "=r"((r)[17]), "=r"((r)[18]), "=r"((r)[19]), \
          "=r"((r)[20]), "=r"((r)[21]), "=r"((r)[22]), "=r"((r)[23]), \
          "=r"((r)[24]), "=r"((r)[25]), "=r"((r)[26]), "=r"((r)[27]), \
          "=r"((r)[28]), "=r"((r)[29]), "=r"((r)[30]), "=r"((r)[31]) \
        : "r"(a))
#endif

// ---------------- weight convert + transpose to fp16 (packed out) ----------------
__global__ void convT(const float* __restrict__ W, fp16* __restrict__ th, int K, int N)
{
    __shared__ float t[32][33];
    int n0 = blockIdx.x * 32, k0 = blockIdx.y * 32;
    int tx = threadIdx.x, ty = threadIdx.y; // (32,8)
    int nck = K >> 6;
#pragma unroll
    for (int r = 0; r < 4; r++) {
        int k = k0 + ty + r * 8;
        t[ty + r * 8][tx] = W[(size_t)k * N + n0 + tx];
    }
    __syncthreads();
#pragma unroll
    for (int r = 0; r < 4; r++) {
        int n = n0 + ty + r * 8;
        th[packB_off(n, k0 + tx, nck)] = __float2half_rn(t[tx][ty + r * 8]);
    }
}

// ---------------- LayerNorm -> split fp16 (packed out) ----------------
__global__ void ln_kernel(const float* __restrict__ h, const float* __restrict__ sc,
                          const float* __restrict__ bi,
                          fp16* __restrict__ xh, fp16* __restrict__ xl)
{
    int row = blockIdx.x;
    const float* hr = h + (size_t)row * DD;
    int tid = threadIdx.x;
    float v0 = hr[tid], v1 = hr[tid + 256], v2 = hr[tid + 512];
    __shared__ float red[256];
    red[tid] = v0 + v1 + v2;
    __syncthreads();
    for (int o = 128; o > 0; o >>= 1) {
        if (tid < o) red[tid] += red[tid + o];
        __syncthreads();
    }
    float mean = red[0] * (1.0f / DD);
    __syncthreads();
    float d0 = v0 - mean, d1 = v1 - mean, d2 = v2 - mean;
    red[tid] = d0 * d0 + d1 * d1 + d2 * d2;
    __syncthreads();
    for (int o = 128; o > 0; o >>= 1) {
        if (tid < o) red[tid] += red[tid + o];
        __syncthreads();
    }
    float rstd = rsqrtf(red[0] * (1.0f / DD) + 1e-5f);
    float y0 = d0 * rstd * sc[tid]       + bi[tid];
    float y1 = d1 * rstd * sc[tid + 256] + bi[tid + 256];
    float y2 = d2 * rstd * sc[tid + 512] + bi[tid + 512];
    fp16 hh, ll;
    size_t o0 = packA_off(row, tid,       12);
    size_t o1 = packA_off(row, tid + 256, 12);
    size_t o2 = packA_off(row, tid + 512, 12);
    split_f16(y0, hh, ll); xh[o0] = hh; xl[o0] = ll;
    split_f16(y1, hh, ll); xh[o1] = hh; xl[o1] = ll;
    split_f16(y2, hh, ll); xh[o2] = hh; xl[o2] = ll;
}

// ---------------- tcgen05 GEMM: C[M,Nc] = A[M,Kd] @ B[Nc,Kd]^T ----------------
// fp16 2-term A-split: Ah*Bh + Al*Bh, fp32 accum in TMEM.
// Tile 128x256, 3-stage 64KB pipeline fed by cp.async.bulk from packed gmem;
// warp-specialized bulk producer (warp0) / MMA issuer (warp1).
// EPI 0: packed QKV store to C0/C1/C2 fp32 (each stride 768)
// EPI 1: gelu(acc + bias) -> split fp16 Oh/Ol (packed A-layout)
// EPI 2: C0 += acc + bias (fp32 residual)
#define GSMEM 197632
#define STAGE_BYTES 65536

template <int EPI>
__global__ void __launch_bounds__(256) mma_gemm(
    const fp16* __restrict__ Ah, const fp16* __restrict__ Al,
    const fp16* __restrict__ Bh,
    const float* __restrict__ bias,
    float* __restrict__ C0, float* __restrict__ C1, float* __restrict__ C2,
    fp16* __restrict__ Oh, fp16* __restrict__ Ol,
    int Kd, int Nc)
{
#if HAS_TCGEN05
    extern __shared__ char sm[];
    const uint32_t smem_base = smem_u32(sm);
    const int tid = threadIdx.x;
    const int bm = blockIdx.y * 128;
    const int bn = blockIdx.x * 256;
    const int NC = Kd >> 6;   // divisible by 3 for Kd=768/3072

    // barriers: full[3] @8,16,24  free[3] @32,40,48  done @56
    if (tid == 0) {
#pragma unroll
        for (int i = 0; i < 7; i++) mbar_init(smem_base + 8 + 8 * i, 1);
    }
    if (tid < 32) { tm_alloc(smem_base, 256); tm_relinq(); }
    __syncthreads();
    uint32_t tmem;
    asm volatile("ld.shared.b32 %0, [%1];" : "=r"(tmem) : "r"(smem_base));

    const uint32_t IDESC = (1u << 4) | ((256u / 8) << 17) | ((128u / 16) << 24);

    if (tid < 32 && elect_one()) {
        // ---- producer: 3 bulk copies per chunk from packed gmem ----
        const char* pAh = (const char*)(Ah + ((size_t)blockIdx.y * NC << 13));
        const char* pAl = (const char*)(Al + ((size_t)blockIdx.y * NC << 13));
        const char* pBh = (const char*)(Bh + ((size_t)blockIdx.x * NC << 14));
        uint32_t fr[3] = {0, 0, 0};
        for (int c = 0; c < NC; c += 3) {
#pragma unroll
            for (int s = 0; s < 3; s++) {
                const int cc = c + s;
                if (c >= 3) { mbar_wait(smem_base + 32 + 8 * s, fr[s]); fr[s] ^= 1; }
                const uint32_t su = smem_base + 1024 + (uint32_t)s * STAGE_BYTES;
                const uint32_t fb = smem_base + 8 + 8 * s;
                mbar_expect_tx(fb, STAGE_BYTES);
                bulk_ld(su,         pAh + ((size_t)cc << 14), 16384, fb);
                bulk_ld(su + 16384, pAl + ((size_t)cc << 14), 16384, fb);
                bulk_ld(su + 32768, pBh + ((size_t)cc << 15), 32768, fb);
            }
        }
    } else if (tid >= 32 && tid < 64 && elect_one()) {
        // ---- consumer: wait stage full, issue 8 MMAs, release stage ----
        uint32_t fp[3] = {0, 0, 0};
        for (int c = 0; c < NC; c += 3) {
#pragma unroll
            for (int s = 0; s < 3; s++) {
                const int cc = c + s;
                mbar_wait(smem_base + 8 + 8 * s, fp[s]); fp[s] ^= 1;
                const uint32_t su = smem_base + 1024 + (uint32_t)s * STAGE_BYTES;
                uint64_t dAh = mkdesc(su);
                uint64_t dAl = mkdesc(su + 16384);
                uint64_t dBh = mkdesc(su + 32768);
#pragma unroll
                for (int ks = 0; ks < 4; ks++)
                    mma_f16_ss(tmem, dAh + ks * 2, dBh + ks * 2, IDESC, (cc > 0) | (ks > 0));
#pragma unroll
                for (int ks = 0; ks < 4; ks++)
                    mma_f16_ss(tmem, dAl + ks * 2, dBh + ks * 2, IDESC, 1);
                tm_commit(smem_base + 32 + 8 * s);
            }
        }
        tm_commit(smem_base + 56);   // all MMAs complete -> done
    }

    // all threads: wait for full accumulation
    mbar_wait(smem_base + 56, 0);
    asm volatile("tcgen05.fence::after_thread_sync;" ::: "memory");

    // stage D through smem (transposed-coalesced writeout)
    const int w = tid >> 5, lane = tid & 31;
    const int cb = (w >> 2) * 128;
    const int r = (w & 3) * 32 + lane;
    float* Cs = (float*)(sm + 1024);
#pragma unroll
    for (int cc = 0; cc < 4; cc++) {
        uint32_t regs[32];
        LDTM_X32(regs, tmem + cb + cc * 32);
        asm volatile("tcgen05.wait::ld.sync.aligned;" ::: "memory");
#pragma unroll
        for (int j = 0; j < 32; j++)
            Cs[r * 257 + cb + cc * 32 + j] = __uint_as_float(regs[j]);
    }
    asm volatile("tcgen05.fence::before_thread_sync;" ::: "memory");
    __syncthreads();

    if (EPI == 0) {
        float* dst; int nb = bn;
        if (nb < 768) dst = C0;
        else if (nb < 1536) { dst = C1; nb -= 768; }
        else { dst = C2; nb -= 1536; }
#pragma unroll 4
        for (int it = 0; it < 128; it++)
            dst[(size_t)(bm + it) * 768 + nb + tid] = Cs[it * 257 + tid];
    } else if (EPI == 1) {
        float bb = bias[bn + tid];
        const int nck = Nc >> 6;
#pragma unroll 4
        for (int it = 0; it < 128; it++) {
            float g = gelu_tanh(Cs[it * 257 + tid] + bb);
            fp16 h, l; split_f16(g, h, l);
            size_t o = packA_off(bm + it, bn + tid, nck);
            Oh[o] = h; Ol[o] = l;
        }
    } else {
        float bb = bias[bn + tid];
#pragma unroll 4
        for (int it = 0; it < 128; it++) {
            size_t o = (size_t)(bm + it) * Nc + bn + tid;
            C0[o] += Cs[it * 257 + tid] + bb;
        }
    }
    __syncthreads();
    if (tid == 0) {
#pragma unroll
        for (int i = 0; i < 7; i++) mbar_inval(smem_base + 8 + 8 * i);
    }
    if (tid < 32) tm_dealloc(tmem, 256);
#else
    // correct-but-slow fallback for the non-arch-specific compile pass
    const int tid = threadIdx.x;
    const int bm = blockIdx.y * 128;
    const int bn = blockIdx.x * 256;
    const int nck = Kd >> 6;
    for (int e = tid; e < 128 * 256; e += 256) {
        int r = e >> 8, c = e & 255;
        float s = 0.f;
        for (int k = 0; k < Kd; k++) {
            size_t ao = packA_off(bm + r, k, nck);
            size_t bo = packB_off(bn + c, k, nck);
            float a = __half2float(Ah[ao]) + __half2float(Al[ao]);
            float b = __half2float(Bh[bo]);
            s += a * b;
        }
        if (EPI == 0) {
            float* dst; int nb = bn + c;
            if (nb < 768) dst = C0;
            else if (nb < 1536) { dst = C1; nb -= 768; }
            else { dst = C2; nb -= 1536; }
            dst[(size_t)(bm + r) * 768 + nb] = s;
        } else if (EPI == 1) {
            float g = gelu_tanh(s + bias[bn + c]);
            fp16 h, l; split_f16(g, h, l);
            size_t o = packA_off(bm + r, bn + c, Nc >> 6);
            Oh[o] = h; Ol[o] = l;
        } else {
            size_t o = (size_t)(bm + r) * Nc + bn + c;
            C0[o] += s + bias[bn + c];
        }
    }
#endif
}

// ---------------- Time attention (T=32), packed fp16 out ----------------
__global__ void __launch_bounds__(32) attn_time_kernel(
    const float* __restrict__ q, const float* __restrict__ k,
    const float* __restrict__ v, fp16* __restrict__ oh, fp16* __restrict__ ol)
{
    __shared__ float Ks[32][64];
    __shared__ float Vs[32][64];
    __shared__ float Qs[64][33];
    int bl = blockIdx.x;
    int h = blockIdx.y;
    int b = bl / LL, l = bl % LL;
    int tid = threadIdx.x;
    size_t colbase = (size_t)h * HD;

    for (int e = tid; e < 32 * 64; e += 32) {
        int j = e >> 6, d = e & 63;
        size_t off = ((size_t)(b * TT + j) * LL + l) * DD + colbase + d;
        Ks[j][d] = k[off];
        Vs[j][d] = v[off];
        Qs[d][j] = q[off];
    }
    __syncwarp();

    float qr[64];
#pragma unroll
    for (int d = 0; d < 64; d++) qr[d] = Qs[d][tid];

    float sc_[32];
#pragma unroll 4
    for (int j = 0; j < 32; j++) {
        float s = 0.f;
        const float4* kr = (const float4*)Ks[j];
#pragma unroll
        for (int d4 = 0; d4 < 16; d4++) {
            float4 kk = kr[d4];
            s += qr[d4 * 4 + 0] * kk.x + qr[d4 * 4 + 1] * kk.y
               + qr[d4 * 4 + 2] * kk.z + qr[d4 * 4 + 3] * kk.w;
        }
        sc_[j] = s * 0.125f;
    }
    float m = sc_[0];
#pragma unroll
    for (int j = 1; j < 32; j++) m = fmaxf(m, sc_[j]);
    float lsum = 0.f;
#pragma unroll
    for (int j = 0; j < 32; j++) { sc_[j] = __expf(sc_[j] - m); lsum += sc_[j]; }
    float inv = 1.0f / lsum;

#pragma unroll
    for (int d4 = 0; d4 < 16; d4++) {
        float ax = 0.f, ay = 0.f, az = 0.f, aw = 0.f;
#pragma unroll
        for (int j = 0; j < 32; j++) {
            float4 vv = ((const float4*)Vs[j])[d4];
            float w = sc_[j];
            ax += w * vv.x; ay += w * vv.y; az += w * vv.z; aw += w * vv.w;
        }
        Qs[d4 * 4 + 0][tid] = ax * inv;
        Qs[d4 * 4 + 1][tid] = ay * inv;
        Qs[d4 * 4 + 2][tid] = az * inv;
        Qs[d4 * 4 + 3][tid] = aw * inv;
    }
    __syncwarp();
    for (int e = tid; e < 32 * 64; e += 32) {
        int j = e >> 6, d = e & 63;
        int mtok = (b * TT + j) * LL + l;
        fp16 h2, l2; split_f16(Qs[d][j], h2, l2);
        size_t o = packA_off(mtok, (int)colbase + d, 12);
        oh[o] = h2; ol[o] = l2;
    }
}

// ---------------- Space attention (L=256), packed fp16 out ----------------
#define SPACE_SMEM ((64 * 257 + 64 * 64 + 64 * 64) * 4)
__global__ void __launch_bounds__(256) attn_space_kernel(
    const float* __restrict__ q, const float* __restrict__ k,
    const float* __restrict__ v, fp16* __restrict__ oh, fp16* __restrict__ ol)
{
    extern __shared__ float smf[];
    float(*Qs)[257] = (float(*)[257])smf;
    float* Ks = smf + 64 * 257;
    float* Vs = Ks + 64 * 64;
    int gid = blockIdx.x;
    int h = gid % HH;
    int bt = gid / HH;
    int tid = threadIdx.x;
    size_t rowbase = (size_t)bt * LL;
    size_t colbase = (size_t)h * HD;

    for (int e = tid; e < 256 * 64; e += 256) {
        int j = e >> 6, d = e & 63;
        Qs[d][j] = q[(rowbase + j) * DD + colbase + d];
    }
    __syncthreads();

    float qr[64];
#pragma unroll
    for (int d = 0; d < 64; d++) qr[d] = Qs[d][tid];

    float m = -1e30f, lsum = 0.f;
    float acc[64];
#pragma unroll
    for (int d = 0; d < 64; d++) acc[d] = 0.f;

    for (int c0 = 0; c0 < LL; c0 += 64) {
        __syncthreads();
        for (int e = tid; e < 64 * 64; e += 256) {
            int j = e >> 6, d = e & 63;
            size_t off = (rowbase + c0 + j) * DD + colbase + d;
            Ks[e] = k[off];
            Vs[e] = v[off];
        }
        __syncthreads();
        for (int j = 0; j < 64; j++) {
            float s = 0.f;
            const float4* kr = (const float4*)(Ks + j * 64);
#pragma unroll
            for (int d4 = 0; d4 < 16; d4++) {
                float4 kk = kr[d4];
                s += qr[d4 * 4 + 0] * kk.x + qr[d4 * 4 + 1] * kk.y
                   + qr[d4 * 4 + 2] * kk.z + qr[d4 * 4 + 3] * kk.w;
            }
            s *= 0.125f;
            float mn = fmaxf(m, s);
            float corr = __expf(m - mn);
            float p = __expf(s - mn);
            lsum = lsum * corr + p;
            m = mn;
            const float4* vr = (const float4*)(Vs + j * 64);
#pragma unroll
            for (int d4 = 0; d4 < 16; d4++) {
                float4 vv = vr[d4];
                acc[d4 * 4 + 0] = acc[d4 * 4 + 0] * corr + p * vv.x;
                acc[d4 * 4 + 1] = acc[d4 * 4 + 1] * corr + p * vv.y;
                acc[d4 * 4 + 2] = acc[d4 * 4 + 2] * corr + p * vv.z;
                acc[d4 * 4 + 3] = acc[d4 * 4 + 3] * corr + p * vv.w;
            }
        }
    }
    float inv = 1.0f / lsum;
    __syncthreads();
#pragma unroll
    for (int d = 0; d < 64; d++) Qs[d][tid] = acc[d] * inv;
    __syncthreads();
    for (int e = tid; e < 256 * 64; e += 256) {
        int j = e >> 6, d = e & 63;
        int mtok = (int)rowbase + j;
        fp16 h2, l2; split_f16(Qs[d][j], h2, l2);
        size_t o = packA_off(mtok, (int)colbase + d, 12);
        oh[o] = h2; ol[o] = l2;
    }
}

// ---------------- host launch ----------------
extern "C" void kernel_launch(void* const* d_in, const int* in_sizes, int n_in,
                              void* d_out, int out_size)
{
    const float* inp   = (const float*)d_in[0];
    const float* Wq_t  = (const float*)d_in[1];
    const float* Wk_t  = (const float*)d_in[2];
    const float* Wv_t  = (const float*)d_in[3];
    const float* Wo_t  = (const float*)d_in[4];
    const float* bo_t  = (const float*)d_in[5];
    const float* Wq_s  = (const float*)d_in[6];
    const float* Wk_s  = (const float*)d_in[7];
    const float* Wv_s  = (const float*)d_in[8];
    const float* Wo_s  = (const float*)d_in[9];
    const float* bo_s  = (const float*)d_in[10];
    const float* ln_ts = (const float*)d_in[11];
    const float* ln_tb = (const float*)d_in[12];
    const float* ln_ss = (const float*)d_in[13];
    const float* ln_sb = (const float*)d_in[14];
    const float* ln2s  = (const float*)d_in[15];
    const float* ln2b  = (const float*)d_in[16];
    const float* W1    = (const float*)d_in[17];
    const float* b1    = (const float*)d_in[18];
    const float* W2    = (const float*)d_in[19];
    const float* b2    = (const float*)d_in[20];
    float* out = (float*)d_out;

    cudaFuncSetAttribute(attn_space_kernel,
                         cudaFuncAttributeMaxDynamicSharedMemorySize, SPACE_SMEM);
    cudaFuncSetAttribute(mma_gemm<0>, cudaFuncAttributeMaxDynamicSharedMemorySize, GSMEM);
    cudaFuncSetAttribute(mma_gemm<1>, cudaFuncAttributeMaxDynamicSharedMemorySize, GSMEM);
    cudaFuncSetAttribute(mma_gemm<2>, cudaFuncAttributeMaxDynamicSharedMemorySize, GSMEM);

    float *gq, *gk, *gv;
    fp16 *gxh, *gxl, *gah, *gal, *gfh, *gfl, *wth;
    cudaGetSymbolAddress((void**)&gq, g_q);
    cudaGetSymbolAddress((void**)&gk, g_k);
    cudaGetSymbolAddress((void**)&gv, g_v);
    cudaGetSymbolAddress((void**)&gxh, g_xh);
    cudaGetSymbolAddress((void**)&gxl, g_xl);
    cudaGetSymbolAddress((void**)&gah, g_ah);
    cudaGetSymbolAddress((void**)&gal, g_al);
    cudaGetSymbolAddress((void**)&gfh, g_ffh);
    cudaGetSymbolAddress((void**)&gfl, g_ffl);
    cudaGetSymbolAddress((void**)&wth, g_wth);

    cudaMemcpyAsync(out, inp, (size_t)NTOK * DD * sizeof(float),
                    cudaMemcpyDeviceToDevice);

    // convert + transpose all weights into packed fp16 tile images
    dim3 cb(32, 8);
    for (int lyr = 0; lyr < NLAYER; lyr++) {
        size_t wo  = (size_t)lyr * DD * DD;
        size_t w1o = (size_t)lyr * DD * FFW_;
        size_t base = (size_t)lyr * WT_LAYER;
        dim3 gdd(DD / 32, DD / 32);
        convT<<<gdd, cb>>>(Wq_t + wo, wth + base + WT_QKV_T,           DD, DD);
        convT<<<gdd, cb>>>(Wk_t + wo, wth + base + WT_QKV_T + 589824,  DD, DD);
        convT<<<gdd, cb>>>(Wv_t + wo, wth + base + WT_QKV_T + 1179648, DD, DD);
        convT<<<gdd, cb>>>(Wq_s + wo, wth + base + WT_QKV_S,           DD, DD);
        convT<<<gdd, cb>>>(Wk_s + wo, wth + base + WT_QKV_S + 589824,  DD, DD);
        convT<<<gdd, cb>>>(Wv_s + wo, wth + base + WT_QKV_S + 1179648, DD, DD);
        convT<<<gdd, cb>>>(Wo_t + wo, wth + base + WT_WO_T, DD, DD);
        convT<<<gdd, cb>>>(Wo_s + wo, wth + base + WT_WO_S, DD, DD);
        convT<<<dim3(FFW_ / 32, DD / 32), cb>>>(W1 + w1o, wth + base + WT_W1, DD, FFW_);
        convT<<<dim3(DD / 32, FFW_ / 32), cb>>>(W2 + w1o, wth + base + WT_W2, FFW_, DD);
    }

    dim3 gQKV(9, 128), gO(3, 128), gF1(12, 128), gF2(3, 128);

    for (int lyr = 0; lyr < NLAYER; lyr++) {
        size_t vo = (size_t)lyr * DD;
        size_t fo = (size_t)lyr * FFW_;
        size_t base = (size_t)lyr * WT_LAYER;

        // ---- time attention block ----
        ln_kernel<<<NTOK, 256>>>(out, ln_ts + vo, ln_tb + vo, gxh, gxl);
        mma_gemm<0><<<gQKV, 256, GSMEM>>>(gxh, gxl, wth + base + WT_QKV_T,
            nullptr, gq, gk, gv, nullptr, nullptr, DD, 2304);
        attn_time_kernel<<<dim3(NB * LL, HH), 32>>>(gq, gk, gv, gah, gal);
        mma_gemm<2><<<gO, 256, GSMEM>>>(gah, gal, wth + base + WT_WO_T,
            bo_t + vo, out, nullptr, nullptr, nullptr, nullptr, DD, DD);

        // ---- space attention block ----
        ln_kernel<<<NTOK, 256>>>(out, ln_ss + vo, ln_sb + vo, gxh, gxl);
        mma_gemm<0><<<gQKV, 256, GSMEM>>>(gxh, gxl, wth + base + WT_QKV_S,
            nullptr, gq, gk, gv, nullptr, nullptr, DD, 2304);
        attn_space_kernel<<<NB * TT * HH, 256, SPACE_SMEM>>>(gq, gk, gv, gah, gal);
        mma_gemm<2><<<gO, 256, GSMEM>>>(gah, gal, wth + base + WT_WO_S,
            bo_s + vo, out, nullptr, nullptr, nullptr, nullptr, DD, DD);

        // ---- FFN block ----
        ln_kernel<<<NTOK, 256>>>(out, ln2s + vo, ln2b + vo, gxh, gxl);
        mma_gemm<1><<<gF1, 256, GSMEM>>>(gxh, gxl, wth + base + WT_W1,
            b1 + fo, nullptr, nullptr, nullptr, gfh, gfl, DD, FFW_);
        mma_gemm<2><<<gF2, 256, GSMEM>>>(gfh, gfl, wth + base + WT_W2,
            b2 + vo, out, nullptr, nullptr, nullptr, nullptr, FFW_, DD);
    }
}